// round 9
// baseline (speedup 1.0000x reference)
#include <cuda_runtime.h>
#include <math.h>
#include <stdint.h>

#define B_    4
#define T_    1000
#define C_    1024
#define H_    16
#define D_    64
#define M_TOK (B_*T_)   // 4000
#define MPAD  4096      // padded row count for A-side buffers

// Scratch (allocation-free: device globals)
__device__ float    g_q[B_*H_*T_*D_];
__device__ float    g_k[B_*H_*T_*D_];
__device__ float    g_v[B_*H_*T_*D_];
__device__ uint32_t g_ya[MPAD*C_];        // attention out, tf32 bits (padded rows stay 0)
__device__ uint32_t g_xa[MPAD*C_];        // x, tf32 bits (padded rows stay 0)
__device__ uint32_t g_wa[C_*3*C_];        // W_attn, tf32 bits
__device__ uint32_t g_wp[C_*C_];          // W_proj, tf32 bits
__device__ float    g_cos[T_*(D_/2)];
__device__ float    g_sin[T_*(D_/2)];

// ---------------------------------------------------------------------------
__device__ __forceinline__ uint32_t f2tf32(float x) {
    uint32_t u;
    asm("cvt.rna.tf32.f32 %0, %1;" : "=r"(u) : "f"(x));
    return u;
}

__device__ __forceinline__ void mma_tf32(float c[4],
                                         const uint32_t a[4],
                                         const uint32_t b[2]) {
    asm volatile(
        "mma.sync.aligned.m16n8k8.row.col.f32.tf32.tf32.f32 "
        "{%0,%1,%2,%3}, {%4,%5,%6,%7}, {%8,%9}, {%0,%1,%2,%3};"
        : "+f"(c[0]), "+f"(c[1]), "+f"(c[2]), "+f"(c[3])
        : "r"(a[0]), "r"(a[1]), "r"(a[2]), "r"(a[3]),
          "r"(b[0]), "r"(b[1]));
}

__device__ __forceinline__ void ldsm_x4(uint32_t r[4], uint32_t smaddr) {
    asm volatile(
        "ldmatrix.sync.aligned.m8n8.x4.shared.b16 {%0,%1,%2,%3}, [%4];"
        : "=r"(r[0]), "=r"(r[1]), "=r"(r[2]), "=r"(r[3])
        : "r"(smaddr));
}

// ---------------------------------------------------------------------------
__global__ void rope_table_kernel() {
    int t = blockIdx.x;
    int i = threadIdx.x;
    float theta = (float)pow(10000.0, -(double)(2 * i) / 64.0);
    float ang = (float)t * theta;
    g_cos[t * 32 + i] = cosf(ang);
    g_sin[t * 32 + i] = sinf(ang);
}

// pre-convert fp32 -> tf32 bits, vectorized
__global__ void cvt_tf32_kernel(const float4* __restrict__ src,
                                uint4* __restrict__ dst, int n4) {
    int i = blockIdx.x * blockDim.x + threadIdx.x;
    if (i < n4) {
        float4 v = src[i];
        dst[i] = make_uint4(f2tf32(v.x), f2tf32(v.y), f2tf32(v.z), f2tf32(v.w));
    }
}

// ---------------------------------------------------------------------------
// 128x128 tf32 GEMM, 4 warps (128 thr), warp tile 64x64, double-buffered.
// A/B already tf32 bits in global. A frags via ldmatrix.x4, B scalar LDS.
//  A smem: [m=128][k=16] u32, stride AST=20.  B smem: [k=16][n=128], stride 136.
// MODE 0: C = x @ W_attn, RoPE epilogue -> g_q/g_k/g_v.  MODE 1: -> Cout f32.
// ---------------------------------------------------------------------------
#define BK   16
#define AST  20
#define LDS_ 136

template<int MODE>
__global__ void __launch_bounds__(128, 2)
gemm_tc(const uint32_t* __restrict__ Abits, const uint32_t* __restrict__ Bbits,
        float* __restrict__ Cout, int M, int N, int K)
{
    __shared__ __align__(16) uint32_t As[2][128 * AST];
    __shared__ __align__(16) uint32_t Bs[2][BK * LDS_];

    const int tid  = threadIdx.x;
    const int warp = tid >> 5;
    const int lane = tid & 31;
    const int g    = lane >> 2;
    const int tg   = lane & 3;
    const int wm   = warp >> 1;      // 0..1
    const int wn   = warp & 1;       // 0..1
    const int wmB  = wm * 64;
    const int wnB  = wn * 64;

    const int bm = blockIdx.y * 128;
    const int bn = blockIdx.x * 128;

    float acc[4][8][4];
#pragma unroll
    for (int mf = 0; mf < 4; mf++)
#pragma unroll
        for (int nf = 0; nf < 8; nf++)
#pragma unroll
            for (int i = 0; i < 4; i++) acc[mf][nf][i] = 0.f;

    // writer indexing
    const int arow = tid;                       // A: one row per thread (padded buf)
    const int brow = (tid >> 5);                // B: rows (tid>>5)+4j
    const int bcol = lane * 4;

    // LDSM lane addressing
    const int rA = (lane & 7) + ((lane >> 3) & 1) * 8;
    const int cA = (lane >> 4) * 4;

    uint4 pa[4], pb[4];

    // prologue: chunk 0 -> stage 0
    {
        const uint32_t* arp = Abits + (size_t)(bm + arow) * K;
#pragma unroll
        for (int j = 0; j < 4; j++) pa[j] = *(const uint4*)(arp + j * 4);
#pragma unroll
        for (int j = 0; j < 4; j++)
            pb[j] = *(const uint4*)(Bbits + (size_t)(brow + 4 * j) * N + bn + bcol);
#pragma unroll
        for (int j = 0; j < 4; j++) *(uint4*)&As[0][arow * AST + j * 4] = pa[j];
#pragma unroll
        for (int j = 0; j < 4; j++) *(uint4*)&Bs[0][(brow + 4 * j) * LDS_ + bcol] = pb[j];
    }
    __syncthreads();

    const int nchunk = K / BK;
    for (int ch = 0; ch < nchunk; ch++) {
        const int cur = ch & 1;
        const int nxt = cur ^ 1;
        const bool have_next = (ch + 1 < nchunk);

        if (have_next) {
            const int k0 = (ch + 1) * BK;
            const uint32_t* arp = Abits + (size_t)(bm + arow) * K + k0;
#pragma unroll
            for (int j = 0; j < 4; j++) pa[j] = *(const uint4*)(arp + j * 4);
#pragma unroll
            for (int j = 0; j < 4; j++)
                pb[j] = *(const uint4*)(Bbits + (size_t)(k0 + brow + 4 * j) * N + bn + bcol);
        }

        const uint32_t asbase = (uint32_t)__cvta_generic_to_shared(&As[cur][0]);

#pragma unroll
        for (int s = 0; s < 2; s++) {
            uint32_t afr[4][4], bfr[8][2];
#pragma unroll
            for (int mf = 0; mf < 4; mf++) {
                uint32_t addr = asbase +
                    (((wmB + mf * 16 + rA) * AST + 8 * s + cA) << 2);
                ldsm_x4(afr[mf], addr);
            }
            const int kr0 = (8 * s + tg) * LDS_;
            const int kr1 = (8 * s + tg + 4) * LDS_;
#pragma unroll
            for (int nf = 0; nf < 8; nf++) {
                int n0 = wnB + nf * 8 + g;
                bfr[nf][0] = Bs[cur][kr0 + n0];
                bfr[nf][1] = Bs[cur][kr1 + n0];
            }
#pragma unroll
            for (int mf = 0; mf < 4; mf++)
#pragma unroll
                for (int nf = 0; nf < 8; nf++)
                    mma_tf32(acc[mf][nf], afr[mf], bfr[nf]);
        }

        if (have_next) {
#pragma unroll
            for (int j = 0; j < 4; j++) *(uint4*)&As[nxt][arow * AST + j * 4] = pa[j];
#pragma unroll
            for (int j = 0; j < 4; j++) *(uint4*)&Bs[nxt][(brow + 4 * j) * LDS_ + bcol] = pb[j];
            __syncthreads();
        }
    }

    // ---------------- epilogue ----------------
    if (MODE == 1) {
#pragma unroll
        for (int mf = 0; mf < 4; mf++) {
#pragma unroll
            for (int half = 0; half < 2; half++) {
                int gr = bm + wmB + mf * 16 + g + half * 8;
                if (gr >= M) continue;
#pragma unroll
                for (int nf = 0; nf < 8; nf++) {
                    int c = bn + wnB + nf * 8 + tg * 2;
                    *(float2*)&Cout[(size_t)gr * N + c] =
                        make_float2(acc[mf][nf][2 * half], acc[mf][nf][2 * half + 1]);
                }
            }
        }
    } else {
        int cwarp = bn + wnB;            // 64-aligned -> single (tensor, head) per warp
        int which = cwarp >> 10;
        int h     = (cwarp & 1023) >> 6;
#pragma unroll
        for (int mf = 0; mf < 4; mf++) {
#pragma unroll
            for (int half = 0; half < 2; half++) {
                int gr = bm + wmB + mf * 16 + g + half * 8;
                if (gr >= M) continue;
                int b = gr / T_;
                int t = gr - b * T_;
                size_t rowbase = ((size_t)(b * H_ + h) * T_ + t) * D_;
#pragma unroll
                for (int nf = 0; nf < 8; nf++) {
                    int dbase = (wnB + nf * 8 + tg * 2) & 63;
                    float x0 = acc[mf][nf][2 * half];
                    float x1 = acc[mf][nf][2 * half + 1];
                    if (which == 2) {
                        *(float2*)&g_v[rowbase + dbase] = make_float2(x0, x1);
                    } else {
                        int pi = dbase >> 1;
                        float ct = g_cos[t * 32 + pi];
                        float st = g_sin[t * 32 + pi];
                        float* dst = (which == 0 ? g_q : g_k) + rowbase + dbase;
                        *(float2*)dst = make_float2(x0 * ct - x1 * st,
                                                    x1 * ct + x0 * st);
                    }
                }
            }
        }
    }
}

// ---------------------------------------------------------------------------
// Tensor-core flash attention (tf32 mma). Same as R8 except the final write
// stores tf32 bits into g_ya (feeds proj GEMM directly).
// ---------------------------------------------------------------------------
#define AP 68   // smem row pad (words)

__global__ void __launch_bounds__(128) attn_tc_kernel() {
    const int qt = (int)gridDim.x - 1 - (int)blockIdx.x;  // heavy tiles first
    const int h  = blockIdx.y;
    const int b  = blockIdx.z;

    __shared__ uint32_t SmA[64 * AP];   // K tile, then P tile (and Q staging)
    __shared__ uint32_t SmV[64 * AP];   // V tile

    const int tid  = threadIdx.x;
    const int warp = tid >> 5;
    const int lane = tid & 31;
    const int g    = lane >> 2;
    const int tg   = lane & 3;
    const int qw   = warp * 16;

    const size_t base = (size_t)(b * H_ + h) * T_ * D_;

    // ---- stage Q tile, extract Q^T B-fragments into registers ----
    float* Qs = (float*)SmA;
#pragma unroll
    for (int u = 0; u < 8; u++) {
        int i  = u * 128 + tid;
        int q  = i >> 4;
        int d4 = (i & 15) * 4;
        int row = min(qt * 64 + q, T_ - 1);
        *(float4*)&Qs[q * AP + d4] = *(const float4*)&g_q[base + (size_t)row * D_ + d4];
    }
    __syncthreads();

    uint32_t qb[8][2][2];
#pragma unroll
    for (int s = 0; s < 8; s++)
#pragma unroll
        for (int nf = 0; nf < 2; nf++) {
            int col = qw + nf * 8 + g;
            qb[s][nf][0] = f2tf32(Qs[col * AP + 8 * s + tg] * 0.125f);
            qb[s][nf][1] = f2tf32(Qs[col * AP + 8 * s + tg + 4] * 0.125f);
        }
    __syncthreads();

    // ---- persistent state ----
    float Ofr[8][4];
#pragma unroll
    for (int nf = 0; nf < 8; nf++)
#pragma unroll
        for (int i = 0; i < 4; i++) Ofr[nf][i] = 0.f;
    float mrun[4] = {-1e30f, -1e30f, -1e30f, -1e30f};
    float lrun[4] = {0.f, 0.f, 0.f, 0.f};

    const int srcl = (g >> 1) & 3;   // shfl source for col->row exchange

    for (int kt = 0; kt <= qt; kt++) {
        const int kb = kt * 64;

#pragma unroll
        for (int u = 0; u < 8; u++) {
            int i  = u * 128 + tid;
            int kv = i >> 4;
            int d4 = (i & 15) * 4;
            int row = min(kb + kv, T_ - 1);
            float4 kk = *(const float4*)&g_k[base + (size_t)row * D_ + d4];
            float4 vv = *(const float4*)&g_v[base + (size_t)row * D_ + d4];
            *(uint4*)&SmA[kv * AP + d4] =
                make_uint4(f2tf32(kk.x), f2tf32(kk.y), f2tf32(kk.z), f2tf32(kk.w));
            *(uint4*)&SmV[kv * AP + d4] =
                make_uint4(f2tf32(vv.x), f2tf32(vv.y), f2tf32(vv.z), f2tf32(vv.w));
        }
        __syncthreads();

        // ---- Phase A: S^T[kv][q] = K · Q^T ----
        float cS[4][2][4];
#pragma unroll
        for (int mf = 0; mf < 4; mf++)
#pragma unroll
            for (int nf = 0; nf < 2; nf++)
#pragma unroll
                for (int i = 0; i < 4; i++) cS[mf][nf][i] = 0.f;

#pragma unroll
        for (int s = 0; s < 8; s++) {
#pragma unroll
            for (int mf = 0; mf < 4; mf++) {
                uint32_t a[4];
                a[0] = SmA[(mf * 16 + g)     * AP + 8 * s + tg];
                a[1] = SmA[(mf * 16 + g + 8) * AP + 8 * s + tg];
                a[2] = SmA[(mf * 16 + g)     * AP + 8 * s + tg + 4];
                a[3] = SmA[(mf * 16 + g + 8) * AP + 8 * s + tg + 4];
                mma_tf32(cS[mf][0], a, qb[s][0]);
                mma_tf32(cS[mf][1], a, qb[s][1]);
            }
        }

        // causal mask (only the diagonal tile has masked entries)
        if (kt == qt) {
#pragma unroll
            for (int mf = 0; mf < 4; mf++)
#pragma unroll
                for (int nf = 0; nf < 2; nf++)
#pragma unroll
                    for (int i = 0; i < 4; i++) {
                        int kvg = kb + mf * 16 + g + (i >> 1) * 8;
                        int qg  = qt * 64 + qw + nf * 8 + 2 * tg + (i & 1);
                        if (kvg > qg) cS[mf][nf][i] = -1e30f;
                    }
        }

        // ---- softmax over q-columns ----
        float tmax[4];
#pragma unroll
        for (int nf = 0; nf < 2; nf++)
#pragma unroll
            for (int e = 0; e < 2; e++) {
                float v = -1e30f;
#pragma unroll
                for (int mf = 0; mf < 4; mf++)
                    v = fmaxf(v, fmaxf(cS[mf][nf][e], cS[mf][nf][2 + e]));
                tmax[nf * 2 + e] = v;
            }
#pragma unroll
        for (int st = 0; st < 4; st++) {
            tmax[st] = fmaxf(tmax[st], __shfl_xor_sync(0xffffffffu, tmax[st], 4));
            tmax[st] = fmaxf(tmax[st], __shfl_xor_sync(0xffffffffu, tmax[st], 8));
            tmax[st] = fmaxf(tmax[st], __shfl_xor_sync(0xffffffffu, tmax[st], 16));
        }
        float fst[4];
#pragma unroll
        for (int st = 0; st < 4; st++) {
            float mnew = fmaxf(mrun[st], tmax[st]);
            fst[st] = __expf(mrun[st] - mnew);
            mrun[st] = mnew;
            lrun[st] *= fst[st];
        }

        // P = exp(S - m), accumulate l partials (per-thread; g-reduced at end)
#pragma unroll
        for (int mf = 0; mf < 4; mf++)
#pragma unroll
            for (int nf = 0; nf < 2; nf++)
#pragma unroll
                for (int i = 0; i < 4; i++) {
                    float p = __expf(cS[mf][nf][i] - mrun[nf * 2 + (i & 1)]);
                    cS[mf][nf][i] = p;
                    lrun[nf * 2 + (i & 1)] += p;
                }

        __syncthreads();   // all warps done reading K tile (SmA) in phase A

        // store P^T -> Ps[q][kv]  (scatter: bank = 8*tg+g, conflict-free)
        uint32_t* Ps = SmA;
#pragma unroll
        for (int mf = 0; mf < 4; mf++)
#pragma unroll
            for (int nf = 0; nf < 2; nf++)
#pragma unroll
                for (int i = 0; i < 4; i++) {
                    int qloc = qw + nf * 8 + 2 * tg + (i & 1);
                    int kv   = mf * 16 + g + (i >> 1) * 8;
                    Ps[qloc * AP + kv] = f2tf32(cS[mf][nf][i]);
                }
        __syncwarp();

        // rescale O by f (exchange col-state -> row-state, 4 shfls)
        {
            float f0 = __shfl_sync(0xffffffffu, fst[0], srcl);
            float f1 = __shfl_sync(0xffffffffu, fst[1], srcl);
            float f2 = __shfl_sync(0xffffffffu, fst[2], srcl);
            float f3 = __shfl_sync(0xffffffffu, fst[3], srcl);
            float fr0 = (g & 1) ? f1 : f0;
            float fr1 = (g & 1) ? f3 : f2;
#pragma unroll
            for (int nf = 0; nf < 8; nf++) {
                Ofr[nf][0] *= fr0;
                Ofr[nf][1] *= fr0;
                Ofr[nf][2] *= fr1;
                Ofr[nf][3] *= fr1;
            }
        }

        // ---- Phase B: O[q][d] += P · V ----
#pragma unroll
        for (int s = 0; s < 8; s++) {
            uint32_t a[4];
            a[0] = Ps[(qw + g)     * AP + 8 * s + tg];
            a[1] = Ps[(qw + g + 8) * AP + 8 * s + tg];
            a[2] = Ps[(qw + g)     * AP + 8 * s + tg + 4];
            a[3] = Ps[(qw + g + 8) * AP + 8 * s + tg + 4];
#pragma unroll
            for (int nf = 0; nf < 8; nf++) {
                uint32_t bb[2];
                bb[0] = SmV[(8 * s + tg)     * AP + nf * 8 + g];
                bb[1] = SmV[(8 * s + tg + 4) * AP + nf * 8 + g];
                mma_tf32(Ofr[nf], a, bb);
            }
        }
        __syncthreads();   // before next tile overwrites SmA/SmV
    }

    // reduce l partials across the 8 g-lanes of each q-column
#pragma unroll
    for (int st = 0; st < 4; st++) {
        lrun[st] += __shfl_xor_sync(0xffffffffu, lrun[st], 4);
        lrun[st] += __shfl_xor_sync(0xffffffffu, lrun[st], 8);
        lrun[st] += __shfl_xor_sync(0xffffffffu, lrun[st], 16);
    }

    // ---- final: exchange l to row ownership, normalize, write tf32 bits ----
    float l0 = __shfl_sync(0xffffffffu, lrun[0], srcl);
    float l1 = __shfl_sync(0xffffffffu, lrun[1], srcl);
    float l2 = __shfl_sync(0xffffffffu, lrun[2], srcl);
    float l3 = __shfl_sync(0xffffffffu, lrun[3], srcl);
    float lr0 = (g & 1) ? l1 : l0;
    float lr1 = (g & 1) ? l3 : l2;
    float inv0 = 1.f / lr0;
    float inv1 = 1.f / lr1;

    int qg0 = qt * 64 + qw + g;
    int qg1 = qg0 + 8;
    if (qg0 < T_) {
        uint32_t* yp = &g_ya[((size_t)(b * T_) + qg0) * C_ + h * D_];
#pragma unroll
        for (int nf = 0; nf < 8; nf++)
            *(uint2*)&yp[nf * 8 + 2 * tg] =
                make_uint2(f2tf32(Ofr[nf][0] * inv0), f2tf32(Ofr[nf][1] * inv0));
    }
    if (qg1 < T_) {
        uint32_t* yp = &g_ya[((size_t)(b * T_) + qg1) * C_ + h * D_];
#pragma unroll
        for (int nf = 0; nf < 8; nf++)
            *(uint2*)&yp[nf * 8 + 2 * tg] =
                make_uint2(f2tf32(Ofr[nf][2] * inv1), f2tf32(Ofr[nf][3] * inv1));
    }
}

// ---------------------------------------------------------------------------
extern "C" void kernel_launch(void* const* d_in, const int* in_sizes, int n_in,
                              void* d_out, int out_size)
{
    const float* x      = (const float*)d_in[0];
    const float* W_attn = (const float*)d_in[2];
    const float* W_proj = (const float*)d_in[3];
    float* out = (float*)d_out;

    rope_table_kernel<<<T_, 32>>>();

    // pre-convert inputs/weights to tf32 bits
    uint32_t* xa; cudaGetSymbolAddress((void**)&xa, g_xa);
    uint32_t* wa; cudaGetSymbolAddress((void**)&wa, g_wa);
    uint32_t* wp; cudaGetSymbolAddress((void**)&wp, g_wp);
    uint32_t* ya; cudaGetSymbolAddress((void**)&ya, g_ya);

    cvt_tf32_kernel<<<(M_TOK*C_/4 + 255)/256, 256>>>((const float4*)x, (uint4*)xa, M_TOK*C_/4);
    cvt_tf32_kernel<<<(C_*3*C_/4 + 255)/256, 256>>>((const float4*)W_attn, (uint4*)wa, C_*3*C_/4);
    cvt_tf32_kernel<<<(C_*C_/4 + 255)/256, 256>>>((const float4*)W_proj, (uint4*)wp, C_*C_/4);

    dim3 g_qkv(3072 / 128, MPAD / 128);            // 24 x 32
    gemm_tc<0><<<g_qkv, 128>>>(xa, wa, nullptr, M_TOK, 3072, 1024);

    dim3 g_attn((T_ + 63) / 64, H_, B_);           // 16 x 16 x 4
    attn_tc_kernel<<<g_attn, 128>>>();

    dim3 g_proj(1024 / 128, MPAD / 128);           // 8 x 32
    gemm_tc<1><<<g_proj, 128>>>(ya, wp, out, M_TOK, 1024, 1024);
}

// round 10
// speedup vs baseline: 1.0239x; 1.0239x over previous
#include <cuda_runtime.h>
#include <math.h>
#include <stdint.h>

#define B_    4
#define T_    1000
#define C_    1024
#define H_    16
#define D_    64
#define M_TOK (B_*T_)   // 4000
#define MPAD  4096      // padded row count for A-side tf32 buffers

// Scratch (allocation-free: device globals)
__device__ float    g_q[B_*H_*T_*D_];
__device__ float    g_k[B_*H_*T_*D_];
__device__ float    g_v[B_*H_*T_*D_];
__device__ uint32_t g_ya[MPAD*C_];        // attention out, tf32 bits (pad rows stay 0)
__device__ uint32_t g_xa[MPAD*C_];        // x, tf32 bits (pad rows stay 0)
__device__ uint32_t g_wa[C_*3*C_];        // W_attn, tf32 bits
__device__ uint32_t g_wp[C_*C_];          // W_proj, tf32 bits
__device__ float    g_cos[T_*(D_/2)];
__device__ float    g_sin[T_*(D_/2)];

// ---------------------------------------------------------------------------
__device__ __forceinline__ uint32_t f2tf32(float x) {
    uint32_t u;
    asm("cvt.rna.tf32.f32 %0, %1;" : "=r"(u) : "f"(x));
    return u;
}

__device__ __forceinline__ void mma_tf32(float c[4],
                                         const uint32_t a[4],
                                         const uint32_t b[2]) {
    asm volatile(
        "mma.sync.aligned.m16n8k8.row.col.f32.tf32.tf32.f32 "
        "{%0,%1,%2,%3}, {%4,%5,%6,%7}, {%8,%9}, {%0,%1,%2,%3};"
        : "+f"(c[0]), "+f"(c[1]), "+f"(c[2]), "+f"(c[3])
        : "r"(a[0]), "r"(a[1]), "r"(a[2]), "r"(a[3]),
          "r"(b[0]), "r"(b[1]));
}

__device__ __forceinline__ void ldsm_x4(uint32_t r[4], uint32_t smaddr) {
    asm volatile(
        "ldmatrix.sync.aligned.m8n8.x4.shared.b16 {%0,%1,%2,%3}, [%4];"
        : "=r"(r[0]), "=r"(r[1]), "=r"(r[2]), "=r"(r[3])
        : "r"(smaddr));
}

__device__ __forceinline__ void cp16(uint32_t smaddr, const void* gptr) {
    asm volatile("cp.async.cg.shared.global [%0], [%1], 16;"
                 :: "r"(smaddr), "l"(gptr));
}
__device__ __forceinline__ void cp_commit() {
    asm volatile("cp.async.commit_group;" ::: "memory");
}
__device__ __forceinline__ void cp_wait0() {
    asm volatile("cp.async.wait_group 0;" ::: "memory");
}

// ---------------------------------------------------------------------------
__global__ void rope_table_kernel() {
    int t = blockIdx.x;
    int i = threadIdx.x;
    float theta = (float)pow(10000.0, -(double)(2 * i) / 64.0);
    float ang = (float)t * theta;
    g_cos[t * 32 + i] = cosf(ang);
    g_sin[t * 32 + i] = sinf(ang);
}

// pre-convert fp32 -> tf32 bits, vectorized
__global__ void cvt_tf32_kernel(const float4* __restrict__ src,
                                uint4* __restrict__ dst, int n4) {
    int i = blockIdx.x * blockDim.x + threadIdx.x;
    if (i < n4) {
        float4 v = src[i];
        dst[i] = make_uint4(f2tf32(v.x), f2tf32(v.y), f2tf32(v.z), f2tf32(v.w));
    }
}

// ---------------------------------------------------------------------------
// 128x128 tf32 GEMM: 256 thr / 8 warps (2m x 4n), warp tile 64x32 (R8 shape),
// inputs pre-converted to tf32 bits, cp.async double-buffered mainloop,
// A fragments via ldmatrix.x4.
//  A smem: [m=128][k=16] u32, stride AST=20.  B smem: [k=16][n=128], stride 136.
// MODE 0: C = x @ W_attn, RoPE epilogue -> g_q/g_k/g_v.  MODE 1: -> Cout f32.
// ---------------------------------------------------------------------------
#define BK   16
#define AST  20
#define LDS_ 136

template<int MODE>
__global__ void __launch_bounds__(256, 2)
gemm_tc(const uint32_t* __restrict__ Abits, const uint32_t* __restrict__ Bbits,
        float* __restrict__ Cout, int M, int N, int K)
{
    __shared__ __align__(16) uint32_t As[2][128 * AST];
    __shared__ __align__(16) uint32_t Bs[2][BK * LDS_];

    const int tid  = threadIdx.x;
    const int warp = tid >> 5;
    const int lane = tid & 31;
    const int g    = lane >> 2;
    const int tg   = lane & 3;
    const int wm   = warp >> 2;      // 0..1
    const int wn   = warp & 3;       // 0..3
    const int wmB  = wm * 64;
    const int wnB  = wn * 32;

    const int bm = blockIdx.y * 128;
    const int bn = blockIdx.x * 128;

    float acc[4][4][4];
#pragma unroll
    for (int mf = 0; mf < 4; mf++)
#pragma unroll
        for (int nf = 0; nf < 4; nf++)
#pragma unroll
            for (int i = 0; i < 4; i++) acc[mf][nf][i] = 0.f;

    // writer indexing (A buffer is MPAD-padded: loads always in-bounds)
    const int arow = tid >> 1;           // 0..127
    const int q0   = (tid & 1) * 8;      // 0 or 8
    const int brow = tid >> 4;           // 0..15
    const int bc0  = (tid & 15) * 8;     // 0..120

    // LDSM lane addressing (A reader)
    const int rA = (lane & 7) + ((lane >> 3) & 1) * 8;
    const int cA = (lane >> 4) * 4;

    const uint32_t asb0 = (uint32_t)__cvta_generic_to_shared(&As[0][0]);
    const uint32_t asb1 = (uint32_t)__cvta_generic_to_shared(&As[1][0]);
    const uint32_t bsb0 = (uint32_t)__cvta_generic_to_shared(&Bs[0][0]);
    const uint32_t bsb1 = (uint32_t)__cvta_generic_to_shared(&Bs[1][0]);

    const uint32_t aoff0 = (uint32_t)((arow * AST + q0) << 2);
    const uint32_t boff0 = (uint32_t)((brow * LDS_ + bc0) << 2);

    // prologue: stage 0
    {
        const uint32_t* ag = Abits + (size_t)(bm + arow) * K + q0;
        const uint32_t* bg = Bbits + (size_t)brow * N + bn + bc0;
        cp16(asb0 + aoff0,      ag);
        cp16(asb0 + aoff0 + 16, ag + 4);
        cp16(bsb0 + boff0,      bg);
        cp16(bsb0 + boff0 + 16, bg + 4);
        cp_commit();
        cp_wait0();
    }
    __syncthreads();

    const int nchunk = K / BK;
    for (int ch = 0; ch < nchunk; ch++) {
        const int cur = ch & 1;
        const bool have_next = (ch + 1 < nchunk);

        // kick off next-stage copies (overlap with compute below)
        if (have_next) {
            const int k0 = (ch + 1) * BK;
            const uint32_t asbn = (cur ? asb0 : asb1);
            const uint32_t bsbn = (cur ? bsb0 : bsb1);
            const uint32_t* ag = Abits + (size_t)(bm + arow) * K + k0 + q0;
            const uint32_t* bg = Bbits + (size_t)(k0 + brow) * N + bn + bc0;
            cp16(asbn + aoff0,      ag);
            cp16(asbn + aoff0 + 16, ag + 4);
            cp16(bsbn + boff0,      bg);
            cp16(bsbn + boff0 + 16, bg + 4);
            cp_commit();
        }

        const uint32_t asbase = (cur ? asb1 : asb0);

        // compute current stage: 2 k-steps of 8
#pragma unroll
        for (int s = 0; s < 2; s++) {
            uint32_t afr[4][4], bfr[4][2];
#pragma unroll
            for (int mf = 0; mf < 4; mf++) {
                uint32_t addr = asbase +
                    (((wmB + mf * 16 + rA) * AST + 8 * s + cA) << 2);
                ldsm_x4(afr[mf], addr);
            }
            const int kr0 = (8 * s + tg) * LDS_;
            const int kr1 = (8 * s + tg + 4) * LDS_;
#pragma unroll
            for (int nf = 0; nf < 4; nf++) {
                int n0 = wnB + nf * 8 + g;
                bfr[nf][0] = Bs[cur][kr0 + n0];
                bfr[nf][1] = Bs[cur][kr1 + n0];
            }
#pragma unroll
            for (int mf = 0; mf < 4; mf++)
#pragma unroll
                for (int nf = 0; nf < 4; nf++)
                    mma_tf32(acc[mf][nf], afr[mf], bfr[nf]);
        }

        if (have_next) {
            cp_wait0();
            __syncthreads();
        }
    }

    // ---------------- epilogue ----------------
    if (MODE == 1) {
#pragma unroll
        for (int mf = 0; mf < 4; mf++) {
#pragma unroll
            for (int half = 0; half < 2; half++) {
                int gr = bm + wmB + mf * 16 + g + half * 8;
                if (gr >= M) continue;
#pragma unroll
                for (int nf = 0; nf < 4; nf++) {
                    int c = bn + wnB + nf * 8 + tg * 2;
                    *(float2*)&Cout[(size_t)gr * N + c] =
                        make_float2(acc[mf][nf][2 * half], acc[mf][nf][2 * half + 1]);
                }
            }
        }
    } else {
        int cwarp = bn + wnB;
        int which = cwarp >> 10;
        int h     = (cwarp & 1023) >> 6;
#pragma unroll
        for (int mf = 0; mf < 4; mf++) {
#pragma unroll
            for (int half = 0; half < 2; half++) {
                int gr = bm + wmB + mf * 16 + g + half * 8;
                if (gr >= M) continue;
                int b = gr / T_;
                int t = gr - b * T_;
                size_t rowbase = ((size_t)(b * H_ + h) * T_ + t) * D_;
#pragma unroll
                for (int nf = 0; nf < 4; nf++) {
                    int dbase = (wnB + nf * 8 + tg * 2) & 63;
                    float x0 = acc[mf][nf][2 * half];
                    float x1 = acc[mf][nf][2 * half + 1];
                    if (which == 2) {
                        *(float2*)&g_v[rowbase + dbase] = make_float2(x0, x1);
                    } else {
                        int pi = dbase >> 1;
                        float ct = g_cos[t * 32 + pi];
                        float st = g_sin[t * 32 + pi];
                        float* dst = (which == 0 ? g_q : g_k) + rowbase + dbase;
                        *(float2*)dst = make_float2(x0 * ct - x1 * st,
                                                    x1 * ct + x0 * st);
                    }
                }
            }
        }
    }
}

// ---------------------------------------------------------------------------
// Tensor-core flash attention (tf32 mma) — R9 version (writes tf32 bits to
// g_ya so the proj GEMM consumes preconverted A directly).
// ---------------------------------------------------------------------------
#define AP 68   // smem row pad (words)

__global__ void __launch_bounds__(128) attn_tc_kernel() {
    const int qt = (int)gridDim.x - 1 - (int)blockIdx.x;  // heavy tiles first
    const int h  = blockIdx.y;
    const int b  = blockIdx.z;

    __shared__ uint32_t SmA[64 * AP];   // K tile, then P tile (and Q staging)
    __shared__ uint32_t SmV[64 * AP];   // V tile

    const int tid  = threadIdx.x;
    const int warp = tid >> 5;
    const int lane = tid & 31;
    const int g    = lane >> 2;
    const int tg   = lane & 3;
    const int qw   = warp * 16;

    const size_t base = (size_t)(b * H_ + h) * T_ * D_;

    // ---- stage Q tile, extract Q^T B-fragments into registers ----
    float* Qs = (float*)SmA;
#pragma unroll
    for (int u = 0; u < 8; u++) {
        int i  = u * 128 + tid;
        int q  = i >> 4;
        int d4 = (i & 15) * 4;
        int row = min(qt * 64 + q, T_ - 1);
        *(float4*)&Qs[q * AP + d4] = *(const float4*)&g_q[base + (size_t)row * D_ + d4];
    }
    __syncthreads();

    uint32_t qb[8][2][2];
#pragma unroll
    for (int s = 0; s < 8; s++)
#pragma unroll
        for (int nf = 0; nf < 2; nf++) {
            int col = qw + nf * 8 + g;
            qb[s][nf][0] = f2tf32(Qs[col * AP + 8 * s + tg] * 0.125f);
            qb[s][nf][1] = f2tf32(Qs[col * AP + 8 * s + tg + 4] * 0.125f);
        }
    __syncthreads();

    // ---- persistent state ----
    float Ofr[8][4];
#pragma unroll
    for (int nf = 0; nf < 8; nf++)
#pragma unroll
        for (int i = 0; i < 4; i++) Ofr[nf][i] = 0.f;
    float mrun[4] = {-1e30f, -1e30f, -1e30f, -1e30f};
    float lrun[4] = {0.f, 0.f, 0.f, 0.f};

    const int srcl = (g >> 1) & 3;   // shfl source for col->row exchange

    for (int kt = 0; kt <= qt; kt++) {
        const int kb = kt * 64;

#pragma unroll
        for (int u = 0; u < 8; u++) {
            int i  = u * 128 + tid;
            int kv = i >> 4;
            int d4 = (i & 15) * 4;
            int row = min(kb + kv, T_ - 1);
            float4 kk = *(const float4*)&g_k[base + (size_t)row * D_ + d4];
            float4 vv = *(const float4*)&g_v[base + (size_t)row * D_ + d4];
            *(uint4*)&SmA[kv * AP + d4] =
                make_uint4(f2tf32(kk.x), f2tf32(kk.y), f2tf32(kk.z), f2tf32(kk.w));
            *(uint4*)&SmV[kv * AP + d4] =
                make_uint4(f2tf32(vv.x), f2tf32(vv.y), f2tf32(vv.z), f2tf32(vv.w));
        }
        __syncthreads();

        // ---- Phase A: S^T[kv][q] = K · Q^T ----
        float cS[4][2][4];
#pragma unroll
        for (int mf = 0; mf < 4; mf++)
#pragma unroll
            for (int nf = 0; nf < 2; nf++)
#pragma unroll
                for (int i = 0; i < 4; i++) cS[mf][nf][i] = 0.f;

#pragma unroll
        for (int s = 0; s < 8; s++) {
#pragma unroll
            for (int mf = 0; mf < 4; mf++) {
                uint32_t a[4];
                a[0] = SmA[(mf * 16 + g)     * AP + 8 * s + tg];
                a[1] = SmA[(mf * 16 + g + 8) * AP + 8 * s + tg];
                a[2] = SmA[(mf * 16 + g)     * AP + 8 * s + tg + 4];
                a[3] = SmA[(mf * 16 + g + 8) * AP + 8 * s + tg + 4];
                mma_tf32(cS[mf][0], a, qb[s][0]);
                mma_tf32(cS[mf][1], a, qb[s][1]);
            }
        }

        // causal mask (only the diagonal tile has masked entries)
        if (kt == qt) {
#pragma unroll
            for (int mf = 0; mf < 4; mf++)
#pragma unroll
                for (int nf = 0; nf < 2; nf++)
#pragma unroll
                    for (int i = 0; i < 4; i++) {
                        int kvg = kb + mf * 16 + g + (i >> 1) * 8;
                        int qg  = qt * 64 + qw + nf * 8 + 2 * tg + (i & 1);
                        if (kvg > qg) cS[mf][nf][i] = -1e30f;
                    }
        }

        // ---- softmax over q-columns ----
        float tmax[4];
#pragma unroll
        for (int nf = 0; nf < 2; nf++)
#pragma unroll
            for (int e = 0; e < 2; e++) {
                float v = -1e30f;
#pragma unroll
                for (int mf = 0; mf < 4; mf++)
                    v = fmaxf(v, fmaxf(cS[mf][nf][e], cS[mf][nf][2 + e]));
                tmax[nf * 2 + e] = v;
            }
#pragma unroll
        for (int st = 0; st < 4; st++) {
            tmax[st] = fmaxf(tmax[st], __shfl_xor_sync(0xffffffffu, tmax[st], 4));
            tmax[st] = fmaxf(tmax[st], __shfl_xor_sync(0xffffffffu, tmax[st], 8));
            tmax[st] = fmaxf(tmax[st], __shfl_xor_sync(0xffffffffu, tmax[st], 16));
        }
        float fst[4];
#pragma unroll
        for (int st = 0; st < 4; st++) {
            float mnew = fmaxf(mrun[st], tmax[st]);
            fst[st] = __expf(mrun[st] - mnew);
            mrun[st] = mnew;
            lrun[st] *= fst[st];
        }

        // P = exp(S - m), accumulate l partials (per-thread; g-reduced at end)
#pragma unroll
        for (int mf = 0; mf < 4; mf++)
#pragma unroll
            for (int nf = 0; nf < 2; nf++)
#pragma unroll
                for (int i = 0; i < 4; i++) {
                    float p = __expf(cS[mf][nf][i] - mrun[nf * 2 + (i & 1)]);
                    cS[mf][nf][i] = p;
                    lrun[nf * 2 + (i & 1)] += p;
                }

        __syncthreads();   // all warps done reading K tile (SmA) in phase A

        // store P^T -> Ps[q][kv]  (scatter: bank = 8*tg+g, conflict-free)
        uint32_t* Ps = SmA;
#pragma unroll
        for (int mf = 0; mf < 4; mf++)
#pragma unroll
            for (int nf = 0; nf < 2; nf++)
#pragma unroll
                for (int i = 0; i < 4; i++) {
                    int qloc = qw + nf * 8 + 2 * tg + (i & 1);
                    int kv   = mf * 16 + g + (i >> 1) * 8;
                    Ps[qloc * AP + kv] = f2tf32(cS[mf][nf][i]);
                }
        __syncwarp();

        // rescale O by f (exchange col-state -> row-state, 4 shfls)
        {
            float f0 = __shfl_sync(0xffffffffu, fst[0], srcl);
            float f1 = __shfl_sync(0xffffffffu, fst[1], srcl);
            float f2 = __shfl_sync(0xffffffffu, fst[2], srcl);
            float f3 = __shfl_sync(0xffffffffu, fst[3], srcl);
            float fr0 = (g & 1) ? f1 : f0;
            float fr1 = (g & 1) ? f3 : f2;
#pragma unroll
            for (int nf = 0; nf < 8; nf++) {
                Ofr[nf][0] *= fr0;
                Ofr[nf][1] *= fr0;
                Ofr[nf][2] *= fr1;
                Ofr[nf][3] *= fr1;
            }
        }

        // ---- Phase B: O[q][d] += P · V ----
#pragma unroll
        for (int s = 0; s < 8; s++) {
            uint32_t a[4];
            a[0] = Ps[(qw + g)     * AP + 8 * s + tg];
            a[1] = Ps[(qw + g + 8) * AP + 8 * s + tg];
            a[2] = Ps[(qw + g)     * AP + 8 * s + tg + 4];
            a[3] = Ps[(qw + g + 8) * AP + 8 * s + tg + 4];
#pragma unroll
            for (int nf = 0; nf < 8; nf++) {
                uint32_t bb[2];
                bb[0] = SmV[(8 * s + tg)     * AP + nf * 8 + g];
                bb[1] = SmV[(8 * s + tg + 4) * AP + nf * 8 + g];
                mma_tf32(Ofr[nf], a, bb);
            }
        }
        __syncthreads();   // before next tile overwrites SmA/SmV
    }

    // reduce l partials across the 8 g-lanes of each q-column
#pragma unroll
    for (int st = 0; st < 4; st++) {
        lrun[st] += __shfl_xor_sync(0xffffffffu, lrun[st], 4);
        lrun[st] += __shfl_xor_sync(0xffffffffu, lrun[st], 8);
        lrun[st] += __shfl_xor_sync(0xffffffffu, lrun[st], 16);
    }

    // ---- final: exchange l to row ownership, normalize, write tf32 bits ----
    float l0 = __shfl_sync(0xffffffffu, lrun[0], srcl);
    float l1 = __shfl_sync(0xffffffffu, lrun[1], srcl);
    float l2 = __shfl_sync(0xffffffffu, lrun[2], srcl);
    float l3 = __shfl_sync(0xffffffffu, lrun[3], srcl);
    float lr0 = (g & 1) ? l1 : l0;
    float lr1 = (g & 1) ? l3 : l2;
    float inv0 = 1.f / lr0;
    float inv1 = 1.f / lr1;

    int qg0 = qt * 64 + qw + g;
    int qg1 = qg0 + 8;
    if (qg0 < T_) {
        uint32_t* yp = &g_ya[((size_t)(b * T_) + qg0) * C_ + h * D_];
#pragma unroll
        for (int nf = 0; nf < 8; nf++)
            *(uint2*)&yp[nf * 8 + 2 * tg] =
                make_uint2(f2tf32(Ofr[nf][0] * inv0), f2tf32(Ofr[nf][1] * inv0));
    }
    if (qg1 < T_) {
        uint32_t* yp = &g_ya[((size_t)(b * T_) + qg1) * C_ + h * D_];
#pragma unroll
        for (int nf = 0; nf < 8; nf++)
            *(uint2*)&yp[nf * 8 + 2 * tg] =
                make_uint2(f2tf32(Ofr[nf][2] * inv1), f2tf32(Ofr[nf][3] * inv1));
    }
}

// ---------------------------------------------------------------------------
extern "C" void kernel_launch(void* const* d_in, const int* in_sizes, int n_in,
                              void* d_out, int out_size)
{
    const float* x      = (const float*)d_in[0];
    const float* W_attn = (const float*)d_in[2];
    const float* W_proj = (const float*)d_in[3];
    float* out = (float*)d_out;

    rope_table_kernel<<<T_, 32>>>();

    uint32_t* xa; cudaGetSymbolAddress((void**)&xa, g_xa);
    uint32_t* wa; cudaGetSymbolAddress((void**)&wa, g_wa);
    uint32_t* wp; cudaGetSymbolAddress((void**)&wp, g_wp);
    uint32_t* ya; cudaGetSymbolAddress((void**)&ya, g_ya);

    cvt_tf32_kernel<<<(M_TOK*C_/4 + 255)/256, 256>>>((const float4*)x, (uint4*)xa, M_TOK*C_/4);
    cvt_tf32_kernel<<<(C_*3*C_/4 + 255)/256, 256>>>((const float4*)W_attn, (uint4*)wa, C_*3*C_/4);
    cvt_tf32_kernel<<<(C_*C_/4 + 255)/256, 256>>>((const float4*)W_proj, (uint4*)wp, C_*C_/4);

    dim3 g_qkv(3072 / 128, MPAD / 128);            // 24 x 32
    gemm_tc<0><<<g_qkv, 256>>>(xa, wa, nullptr, M_TOK, 3072, 1024);

    dim3 g_attn((T_ + 63) / 64, H_, B_);           // 16 x 16 x 4
    attn_tc_kernel<<<g_attn, 128>>>();

    dim3 g_proj(1024 / 128, MPAD / 128);           // 8 x 32
    gemm_tc<1><<<g_proj, 256>>>(ya, wp, out, M_TOK, 1024, 1024);
}

// round 12
// speedup vs baseline: 1.0316x; 1.0075x over previous
#include <cuda_runtime.h>
#include <math.h>
#include <stdint.h>

#define B_    4
#define T_    1000
#define C_    1024
#define H_    16
#define D_    64
#define M_TOK (B_*T_)   // 4000
#define MPAD  4096      // padded row count for A-side tf32 buffers

// Scratch (allocation-free: device globals; zero-init -> pad rows stay 0)
__device__ float    g_q[B_*H_*T_*D_];
__device__ float    g_k[B_*H_*T_*D_];
__device__ float    g_v[B_*H_*T_*D_];
__device__ uint32_t g_ya[MPAD*C_];        // attention out, tf32 bits
__device__ uint32_t g_xa[MPAD*C_];        // x, tf32 bits
__device__ uint32_t g_wa[C_*3*C_];        // W_attn, tf32 bits
__device__ uint32_t g_wp[C_*C_];          // W_proj, tf32 bits
__device__ float    g_cos[T_*(D_/2)];
__device__ float    g_sin[T_*(D_/2)];

// ---------------------------------------------------------------------------
__device__ __forceinline__ uint32_t f2tf32(float x) {
    uint32_t u;
    asm("cvt.rna.tf32.f32 %0, %1;" : "=r"(u) : "f"(x));
    return u;
}

__device__ __forceinline__ void mma_tf32(float c[4],
                                         const uint32_t a[4],
                                         const uint32_t b[2]) {
    asm volatile(
        "mma.sync.aligned.m16n8k8.row.col.f32.tf32.tf32.f32 "
        "{%0,%1,%2,%3}, {%4,%5,%6,%7}, {%8,%9}, {%0,%1,%2,%3};"
        : "+f"(c[0]), "+f"(c[1]), "+f"(c[2]), "+f"(c[3])
        : "r"(a[0]), "r"(a[1]), "r"(a[2]), "r"(a[3]),
          "r"(b[0]), "r"(b[1]));
}

__device__ __forceinline__ void ldsm_x4(uint32_t r[4], uint32_t smaddr) {
    asm volatile(
        "ldmatrix.sync.aligned.m8n8.x4.shared.b16 {%0,%1,%2,%3}, [%4];"
        : "=r"(r[0]), "=r"(r[1]), "=r"(r[2]), "=r"(r[3])
        : "r"(smaddr));
}

__device__ __forceinline__ void cp16(uint32_t smaddr, const void* gptr) {
    asm volatile("cp.async.cg.shared.global [%0], [%1], 16;"
                 :: "r"(smaddr), "l"(gptr));
}
__device__ __forceinline__ void cp_commit() {
    asm volatile("cp.async.commit_group;" ::: "memory");
}
__device__ __forceinline__ void cp_wait2() {
    asm volatile("cp.async.wait_group 2;" ::: "memory");
}

// ---------------------------------------------------------------------------
__global__ void rope_table_kernel() {
    int t = blockIdx.x;
    int i = threadIdx.x;
    float theta = (float)pow(10000.0, -(double)(2 * i) / 64.0);
    float ang = (float)t * theta;
    g_cos[t * 32 + i] = cosf(ang);
    g_sin[t * 32 + i] = sinf(ang);
}

__global__ void cvt_tf32_kernel(const float4* __restrict__ src,
                                uint4* __restrict__ dst, int n4) {
    int i = blockIdx.x * blockDim.x + threadIdx.x;
    if (i < n4) {
        float4 v = src[i];
        dst[i] = make_uint4(f2tf32(v.x), f2tf32(v.y), f2tf32(v.z), f2tf32(v.w));
    }
}

// ---------------------------------------------------------------------------
// 128x128 tf32 GEMM: 256 thr / 8 warps (2m x 4n), warp tile 64x32,
// 4-stage cp.async pipeline (dynamic smem), LDSM A-feed.
//  A smem: [m=128][k=16] u32, stride AST=20.  B smem: [k=16][n=128], stride 136.
// MODE 0: C = x @ W_attn, RoPE epilogue -> g_q/g_k/g_v.  MODE 1: -> Cout f32.
// ---------------------------------------------------------------------------
#define BK    16
#define AST   20
#define LDS_  136
#define A_BYTES (128 * AST * 4)              // 10240
#define B_BYTES (BK * LDS_ * 4)              // 8704
#define STG_BYTES (A_BYTES + B_BYTES)        // 18944 (128B-aligned)
#define NSTAGE 4
#define GEMM_SMEM (NSTAGE * STG_BYTES)       // 75776

template<int MODE>
__global__ void __launch_bounds__(256, 2)
gemm_tc(const uint32_t* __restrict__ Abits, const uint32_t* __restrict__ Bbits,
        float* __restrict__ Cout, int M, int N, int K)
{
    extern __shared__ __align__(16) uint8_t dsm[];
    const uint32_t smb = (uint32_t)__cvta_generic_to_shared(dsm);

    const int tid  = threadIdx.x;
    const int warp = tid >> 5;
    const int lane = tid & 31;
    const int g    = lane >> 2;
    const int tg   = lane & 3;
    const int wm   = warp >> 2;      // 0..1
    const int wn   = warp & 3;       // 0..3
    const int wmB  = wm * 64;
    const int wnB  = wn * 32;

    const int bm = blockIdx.y * 128;
    const int bn = blockIdx.x * 128;

    float acc[4][4][4];
#pragma unroll
    for (int mf = 0; mf < 4; mf++)
#pragma unroll
        for (int nf = 0; nf < 4; nf++)
#pragma unroll
            for (int i = 0; i < 4; i++) acc[mf][nf][i] = 0.f;

    // writer indexing (A buffer MPAD-padded: always in-bounds)
    const int arow = tid >> 1;
    const int q0   = (tid & 1) * 8;
    const int brow = tid >> 4;
    const int bc0  = (tid & 15) * 8;

    const uint32_t aoff = (uint32_t)((arow * AST + q0) << 2);
    const uint32_t boff = (uint32_t)(A_BYTES + ((brow * LDS_ + bc0) << 2));

    // LDSM lane addressing
    const int rA = (lane & 7) + ((lane >> 3) & 1) * 8;
    const int cA = (lane >> 4) * 4;

    const int nchunk = K / BK;

    // issue one chunk's copies into stage s
    auto issue = [&](int ch, int s) {
        const int k0 = ch * BK;
        const uint32_t sb = smb + (uint32_t)(s * STG_BYTES);
        const uint32_t* ag = Abits + (size_t)(bm + arow) * K + k0 + q0;
        const uint32_t* bg = Bbits + (size_t)(k0 + brow) * N + bn + bc0;
        cp16(sb + aoff,      ag);
        cp16(sb + aoff + 16, ag + 4);
        cp16(sb + boff,      bg);
        cp16(sb + boff + 16, bg + 4);
        cp_commit();
    };

    // prologue: fill 3 stages
#pragma unroll
    for (int p = 0; p < 3; p++) issue(p, p);

    for (int ch = 0; ch < nchunk; ch++) {
        const int cur = ch & 3;

        cp_wait2();          // stage `ch` complete (in-order group retirement)
        __syncthreads();     // all warps done with the stage being overwritten

        if (ch + 3 < nchunk) issue(ch + 3, (ch + 3) & 3);

        const uint32_t sb = smb + (uint32_t)(cur * STG_BYTES);
        const uint32_t* BsC = (const uint32_t*)(dsm + cur * STG_BYTES + A_BYTES);

#pragma unroll
        for (int s = 0; s < 2; s++) {
            uint32_t afr[4][4], bfr[4][2];
#pragma unroll
            for (int mf = 0; mf < 4; mf++) {
                uint32_t addr = sb +
                    (((wmB + mf * 16 + rA) * AST + 8 * s + cA) << 2);
                ldsm_x4(afr[mf], addr);
            }
            const int kr0 = (8 * s + tg) * LDS_;
            const int kr1 = (8 * s + tg + 4) * LDS_;
#pragma unroll
            for (int nf = 0; nf < 4; nf++) {
                int n0 = wnB + nf * 8 + g;
                bfr[nf][0] = BsC[kr0 + n0];
                bfr[nf][1] = BsC[kr1 + n0];
            }
#pragma unroll
            for (int mf = 0; mf < 4; mf++)
#pragma unroll
                for (int nf = 0; nf < 4; nf++)
                    mma_tf32(acc[mf][nf], afr[mf], bfr[nf]);
        }
    }

    // ---------------- epilogue ----------------
    if (MODE == 1) {
#pragma unroll
        for (int mf = 0; mf < 4; mf++) {
#pragma unroll
            for (int half = 0; half < 2; half++) {
                int gr = bm + wmB + mf * 16 + g + half * 8;
                if (gr >= M) continue;
#pragma unroll
                for (int nf = 0; nf < 4; nf++) {
                    int c = bn + wnB + nf * 8 + tg * 2;
                    *(float2*)&Cout[(size_t)gr * N + c] =
                        make_float2(acc[mf][nf][2 * half], acc[mf][nf][2 * half + 1]);
                }
            }
        }
    } else {
        int cwarp = bn + wnB;
        int which = cwarp >> 10;
        int h     = (cwarp & 1023) >> 6;
#pragma unroll
        for (int mf = 0; mf < 4; mf++) {
#pragma unroll
            for (int half = 0; half < 2; half++) {
                int gr = bm + wmB + mf * 16 + g + half * 8;
                if (gr >= M) continue;
                int b = gr / T_;
                int t = gr - b * T_;
                size_t rowbase = ((size_t)(b * H_ + h) * T_ + t) * D_;
#pragma unroll
                for (int nf = 0; nf < 4; nf++) {
                    int dbase = (wnB + nf * 8 + tg * 2) & 63;
                    float x0 = acc[mf][nf][2 * half];
                    float x1 = acc[mf][nf][2 * half + 1];
                    if (which == 2) {
                        *(float2*)&g_v[rowbase + dbase] = make_float2(x0, x1);
                    } else {
                        int pi = dbase >> 1;
                        float ct = g_cos[t * 32 + pi];
                        float st = g_sin[t * 32 + pi];
                        float* dst = (which == 0 ? g_q : g_k) + rowbase + dbase;
                        *(float2*)dst = make_float2(x0 * ct - x1 * st,
                                                    x1 * ct + x0 * st);
                    }
                }
            }
        }
    }
}

// ---------------------------------------------------------------------------
// Tensor-core flash attention (tf32 mma.sync) — known good; writes tf32 bits
// into g_ya so the proj GEMM consumes preconverted A directly.
// ---------------------------------------------------------------------------
#define AP 68   // smem row pad (words)

__global__ void __launch_bounds__(128) attn_tc_kernel() {
    const int qt = (int)gridDim.x - 1 - (int)blockIdx.x;  // heavy tiles first
    const int h  = blockIdx.y;
    const int b  = blockIdx.z;

    __shared__ uint32_t SmA[64 * AP];   // K tile, then P tile (and Q staging)
    __shared__ uint32_t SmV[64 * AP];   // V tile

    const int tid  = threadIdx.x;
    const int warp = tid >> 5;
    const int lane = tid & 31;
    const int g    = lane >> 2;
    const int tg   = lane & 3;
    const int qw   = warp * 16;

    const size_t base = (size_t)(b * H_ + h) * T_ * D_;

    float* Qs = (float*)SmA;
#pragma unroll
    for (int u = 0; u < 8; u++) {
        int i  = u * 128 + tid;
        int q  = i >> 4;
        int d4 = (i & 15) * 4;
        int row = min(qt * 64 + q, T_ - 1);
        *(float4*)&Qs[q * AP + d4] = *(const float4*)&g_q[base + (size_t)row * D_ + d4];
    }
    __syncthreads();

    uint32_t qb[8][2][2];
#pragma unroll
    for (int s = 0; s < 8; s++)
#pragma unroll
        for (int nf = 0; nf < 2; nf++) {
            int col = qw + nf * 8 + g;
            qb[s][nf][0] = f2tf32(Qs[col * AP + 8 * s + tg] * 0.125f);
            qb[s][nf][1] = f2tf32(Qs[col * AP + 8 * s + tg + 4] * 0.125f);
        }
    __syncthreads();

    float Ofr[8][4];
#pragma unroll
    for (int nf = 0; nf < 8; nf++)
#pragma unroll
        for (int i = 0; i < 4; i++) Ofr[nf][i] = 0.f;
    float mrun[4] = {-1e30f, -1e30f, -1e30f, -1e30f};
    float lrun[4] = {0.f, 0.f, 0.f, 0.f};

    const int srcl = (g >> 1) & 3;

    for (int kt = 0; kt <= qt; kt++) {
        const int kb = kt * 64;

#pragma unroll
        for (int u = 0; u < 8; u++) {
            int i  = u * 128 + tid;
            int kv = i >> 4;
            int d4 = (i & 15) * 4;
            int row = min(kb + kv, T_ - 1);
            float4 kk = *(const float4*)&g_k[base + (size_t)row * D_ + d4];
            float4 vv = *(const float4*)&g_v[base + (size_t)row * D_ + d4];
            *(uint4*)&SmA[kv * AP + d4] =
                make_uint4(f2tf32(kk.x), f2tf32(kk.y), f2tf32(kk.z), f2tf32(kk.w));
            *(uint4*)&SmV[kv * AP + d4] =
                make_uint4(f2tf32(vv.x), f2tf32(vv.y), f2tf32(vv.z), f2tf32(vv.w));
        }
        __syncthreads();

        float cS[4][2][4];
#pragma unroll
        for (int mf = 0; mf < 4; mf++)
#pragma unroll
            for (int nf = 0; nf < 2; nf++)
#pragma unroll
                for (int i = 0; i < 4; i++) cS[mf][nf][i] = 0.f;

#pragma unroll
        for (int s = 0; s < 8; s++) {
#pragma unroll
            for (int mf = 0; mf < 4; mf++) {
                uint32_t a[4];
                a[0] = SmA[(mf * 16 + g)     * AP + 8 * s + tg];
                a[1] = SmA[(mf * 16 + g + 8) * AP + 8 * s + tg];
                a[2] = SmA[(mf * 16 + g)     * AP + 8 * s + tg + 4];
                a[3] = SmA[(mf * 16 + g + 8) * AP + 8 * s + tg + 4];
                mma_tf32(cS[mf][0], a, qb[s][0]);
                mma_tf32(cS[mf][1], a, qb[s][1]);
            }
        }

        if (kt == qt) {
#pragma unroll
            for (int mf = 0; mf < 4; mf++)
#pragma unroll
                for (int nf = 0; nf < 2; nf++)
#pragma unroll
                    for (int i = 0; i < 4; i++) {
                        int kvg = kb + mf * 16 + g + (i >> 1) * 8;
                        int qg  = qt * 64 + qw + nf * 8 + 2 * tg + (i & 1);
                        if (kvg > qg) cS[mf][nf][i] = -1e30f;
                    }
        }

        float tmax[4];
#pragma unroll
        for (int nf = 0; nf < 2; nf++)
#pragma unroll
            for (int e = 0; e < 2; e++) {
                float v = -1e30f;
#pragma unroll
                for (int mf = 0; mf < 4; mf++)
                    v = fmaxf(v, fmaxf(cS[mf][nf][e], cS[mf][nf][2 + e]));
                tmax[nf * 2 + e] = v;
            }
#pragma unroll
        for (int st = 0; st < 4; st++) {
            tmax[st] = fmaxf(tmax[st], __shfl_xor_sync(0xffffffffu, tmax[st], 4));
            tmax[st] = fmaxf(tmax[st], __shfl_xor_sync(0xffffffffu, tmax[st], 8));
            tmax[st] = fmaxf(tmax[st], __shfl_xor_sync(0xffffffffu, tmax[st], 16));
        }
        float fst[4];
#pragma unroll
        for (int st = 0; st < 4; st++) {
            float mnew = fmaxf(mrun[st], tmax[st]);
            fst[st] = __expf(mrun[st] - mnew);
            mrun[st] = mnew;
            lrun[st] *= fst[st];
        }

#pragma unroll
        for (int mf = 0; mf < 4; mf++)
#pragma unroll
            for (int nf = 0; nf < 2; nf++)
#pragma unroll
                for (int i = 0; i < 4; i++) {
                    float p = __expf(cS[mf][nf][i] - mrun[nf * 2 + (i & 1)]);
                    cS[mf][nf][i] = p;
                    lrun[nf * 2 + (i & 1)] += p;
                }

        __syncthreads();

        uint32_t* Ps = SmA;
#pragma unroll
        for (int mf = 0; mf < 4; mf++)
#pragma unroll
            for (int nf = 0; nf < 2; nf++)
#pragma unroll
                for (int i = 0; i < 4; i++) {
                    int qloc = qw + nf * 8 + 2 * tg + (i & 1);
                    int kv   = mf * 16 + g + (i >> 1) * 8;
                    Ps[qloc * AP + kv] = f2tf32(cS[mf][nf][i]);
                }
        __syncwarp();

        {
            float f0 = __shfl_sync(0xffffffffu, fst[0], srcl);
            float f1 = __shfl_sync(0xffffffffu, fst[1], srcl);
            float f2 = __shfl_sync(0xffffffffu, fst[2], srcl);
            float f3 = __shfl_sync(0xffffffffu, fst[3], srcl);
            float fr0 = (g & 1) ? f1 : f0;
            float fr1 = (g & 1) ? f3 : f2;
#pragma unroll
            for (int nf = 0; nf < 8; nf++) {
                Ofr[nf][0] *= fr0;
                Ofr[nf][1] *= fr0;
                Ofr[nf][2] *= fr1;
                Ofr[nf][3] *= fr1;
            }
        }

#pragma unroll
        for (int s = 0; s < 8; s++) {
            uint32_t a[4];
            a[0] = Ps[(qw + g)     * AP + 8 * s + tg];
            a[1] = Ps[(qw + g + 8) * AP + 8 * s + tg];
            a[2] = Ps[(qw + g)     * AP + 8 * s + tg + 4];
            a[3] = Ps[(qw + g + 8) * AP + 8 * s + tg + 4];
#pragma unroll
            for (int nf = 0; nf < 8; nf++) {
                uint32_t bb[2];
                bb[0] = SmV[(8 * s + tg)     * AP + nf * 8 + g];
                bb[1] = SmV[(8 * s + tg + 4) * AP + nf * 8 + g];
                mma_tf32(Ofr[nf], a, bb);
            }
        }
        __syncthreads();
    }

#pragma unroll
    for (int st = 0; st < 4; st++) {
        lrun[st] += __shfl_xor_sync(0xffffffffu, lrun[st], 4);
        lrun[st] += __shfl_xor_sync(0xffffffffu, lrun[st], 8);
        lrun[st] += __shfl_xor_sync(0xffffffffu, lrun[st], 16);
    }

    float l0 = __shfl_sync(0xffffffffu, lrun[0], srcl);
    float l1 = __shfl_sync(0xffffffffu, lrun[1], srcl);
    float l2 = __shfl_sync(0xffffffffu, lrun[2], srcl);
    float l3 = __shfl_sync(0xffffffffu, lrun[3], srcl);
    float lr0 = (g & 1) ? l1 : l0;
    float lr1 = (g & 1) ? l3 : l2;
    float inv0 = 1.f / lr0;
    float inv1 = 1.f / lr1;

    int qg0 = qt * 64 + qw + g;
    int qg1 = qg0 + 8;
    if (qg0 < T_) {
        uint32_t* yp = &g_ya[((size_t)(b * T_) + qg0) * C_ + h * D_];
#pragma unroll
        for (int nf = 0; nf < 8; nf++)
            *(uint2*)&yp[nf * 8 + 2 * tg] =
                make_uint2(f2tf32(Ofr[nf][0] * inv0), f2tf32(Ofr[nf][1] * inv0));
    }
    if (qg1 < T_) {
        uint32_t* yp = &g_ya[((size_t)(b * T_) + qg1) * C_ + h * D_];
#pragma unroll
        for (int nf = 0; nf < 8; nf++)
            *(uint2*)&yp[nf * 8 + 2 * tg] =
                make_uint2(f2tf32(Ofr[nf][2] * inv1), f2tf32(Ofr[nf][3] * inv1));
    }
}

// ---------------------------------------------------------------------------
extern "C" void kernel_launch(void* const* d_in, const int* in_sizes, int n_in,
                              void* d_out, int out_size)
{
    const float* x      = (const float*)d_in[0];
    const float* W_attn = (const float*)d_in[2];
    const float* W_proj = (const float*)d_in[3];
    float* out = (float*)d_out;

    uint32_t* xa; cudaGetSymbolAddress((void**)&xa, g_xa);
    uint32_t* wa; cudaGetSymbolAddress((void**)&wa, g_wa);
    uint32_t* wp; cudaGetSymbolAddress((void**)&wp, g_wp);
    uint32_t* ya; cudaGetSymbolAddress((void**)&ya, g_ya);

    cudaFuncSetAttribute(gemm_tc<0>, cudaFuncAttributeMaxDynamicSharedMemorySize, GEMM_SMEM);
    cudaFuncSetAttribute(gemm_tc<1>, cudaFuncAttributeMaxDynamicSharedMemorySize, GEMM_SMEM);

    rope_table_kernel<<<T_, 32>>>();

    cvt_tf32_kernel<<<(M_TOK*C_/4 + 255)/256, 256>>>((const float4*)x, (uint4*)xa, M_TOK*C_/4);
    cvt_tf32_kernel<<<(C_*3*C_/4 + 255)/256, 256>>>((const float4*)W_attn, (uint4*)wa, C_*3*C_/4);
    cvt_tf32_kernel<<<(C_*C_/4 + 255)/256, 256>>>((const float4*)W_proj, (uint4*)wp, C_*C_/4);

    dim3 g_qkv(3072 / 128, MPAD / 128);            // 24 x 32
    gemm_tc<0><<<g_qkv, 256, GEMM_SMEM>>>(xa, wa, nullptr, M_TOK, 3072, 1024);

    dim3 g_attn((T_ + 63) / 64, H_, B_);           // 16 x 16 x 4
    attn_tc_kernel<<<g_attn, 128>>>();

    dim3 g_proj(1024 / 128, MPAD / 128);           // 8 x 32
    gemm_tc<1><<<g_proj, 256, GEMM_SMEM>>>(ya, wp, out, M_TOK, 1024, 1024);
}

// round 13
// speedup vs baseline: 1.4010x; 1.3581x over previous
#include <cuda_runtime.h>
#include <cuda_fp16.h>
#include <math.h>
#include <stdint.h>

#define B_    4
#define T_    1000
#define C_    1024
#define H_    16
#define D_    64
#define M_TOK (B_*T_)   // 4000
#define MPAD  4096      // padded row count for A-side fp16 buffers

// Scratch (allocation-free device globals; zero-init -> pad rows are 0)
__device__ float  g_q[B_*H_*T_*D_];
__device__ float  g_k[B_*H_*T_*D_];
__device__ float  g_v[B_*H_*T_*D_];
__device__ __half g_xa[MPAD*C_];     // x, fp16
__device__ __half g_ya[MPAD*C_];     // attention out, fp16
__device__ __half g_wat[3*C_*C_];    // W_attn^T [3072][1024] fp16
__device__ __half g_wpt[C_*C_];      // W_proj^T [1024][1024] fp16
__device__ float  g_cos[T_*(D_/2)];
__device__ float  g_sin[T_*(D_/2)];

// ---------------------------------------------------------------------------
__device__ __forceinline__ uint32_t f2tf32(float x) {
    uint32_t u;
    asm("cvt.rna.tf32.f32 %0, %1;" : "=r"(u) : "f"(x));
    return u;
}

__device__ __forceinline__ void mma_f16(float c[4],
                                        const uint32_t a[4],
                                        const uint32_t b[2]) {
    asm volatile(
        "mma.sync.aligned.m16n8k16.row.col.f32.f16.f16.f32 "
        "{%0,%1,%2,%3}, {%4,%5,%6,%7}, {%8,%9}, {%0,%1,%2,%3};"
        : "+f"(c[0]), "+f"(c[1]), "+f"(c[2]), "+f"(c[3])
        : "r"(a[0]), "r"(a[1]), "r"(a[2]), "r"(a[3]),
          "r"(b[0]), "r"(b[1]));
}

__device__ __forceinline__ void mma_tf32(float c[4],
                                         const uint32_t a[4],
                                         const uint32_t b[2]) {
    asm volatile(
        "mma.sync.aligned.m16n8k8.row.col.f32.tf32.tf32.f32 "
        "{%0,%1,%2,%3}, {%4,%5,%6,%7}, {%8,%9}, {%0,%1,%2,%3};"
        : "+f"(c[0]), "+f"(c[1]), "+f"(c[2]), "+f"(c[3])
        : "r"(a[0]), "r"(a[1]), "r"(a[2]), "r"(a[3]),
          "r"(b[0]), "r"(b[1]));
}

__device__ __forceinline__ void ldsm_x4(uint32_t r[4], uint32_t smaddr) {
    asm volatile(
        "ldmatrix.sync.aligned.m8n8.x4.shared.b16 {%0,%1,%2,%3}, [%4];"
        : "=r"(r[0]), "=r"(r[1]), "=r"(r[2]), "=r"(r[3])
        : "r"(smaddr));
}

// ---------------------------------------------------------------------------
__global__ void rope_table_kernel() {
    int t = blockIdx.x;
    int i = threadIdx.x;
    float theta = (float)pow(10000.0, -(double)(2 * i) / 64.0);
    float ang = (float)t * theta;
    g_cos[t * 32 + i] = cosf(ang);
    g_sin[t * 32 + i] = sinf(ang);
}

// f32 -> fp16, vectorized (4 floats -> 4 halves per thread)
__global__ void cvt_h_kernel(const float4* __restrict__ src,
                             uint2* __restrict__ dst, int n4) {
    int i = blockIdx.x * blockDim.x + threadIdx.x;
    if (i < n4) {
        float4 v = src[i];
        __half2 h0 = __floats2half2_rn(v.x, v.y);
        __half2 h1 = __floats2half2_rn(v.z, v.w);
        uint2 o;
        o.x = *(uint32_t*)&h0;
        o.y = *(uint32_t*)&h1;
        dst[i] = o;
    }
}

// src[K][N] f32 -> dst[N][K] fp16
__global__ void transpose_h_kernel(const float* __restrict__ src,
                                   __half* __restrict__ dst,
                                   int K, int N) {
    __shared__ float tile[32][33];
    int n0 = blockIdx.x * 32, k0 = blockIdx.y * 32;
    int tx = threadIdx.x, ty = threadIdx.y;
#pragma unroll
    for (int j = 0; j < 32; j += 8)
        tile[ty + j][tx] = src[(size_t)(k0 + ty + j) * N + n0 + tx];
    __syncthreads();
#pragma unroll
    for (int j = 0; j < 32; j += 8)
        dst[(size_t)(n0 + ty + j) * K + k0 + tx] = __float2half(tile[tx][ty + j]);
}

// ---------------------------------------------------------------------------
// 128x128 fp16 GEMM (f32 accum): 256 thr / 8 warps (2m x 4n), warp 64x32,
// m16n8k16, BK=32 (2 k-steps of 16), double-buffered LDG->STS (R8 style).
//  A smem: [m=128][k=32 halves], row stride 40 halves (80B) -> LDSM conflict-free.
//  B smem: [n=128][k=32 halves], row stride 40 halves -> vector B reads conflict-free.
//  B global: PRE-TRANSPOSED [N][K] fp16.
// MODE 0: C = x @ W_attn, RoPE epilogue -> g_q/g_k/g_v.  MODE 1: -> Cout f32.
// ---------------------------------------------------------------------------
#define BKH  32
#define ASTH 40

template<int MODE>
__global__ void __launch_bounds__(256, 2)
gemm_f16(const __half* __restrict__ A, const __half* __restrict__ Bt,
         float* __restrict__ Cout, int M, int N, int K)
{
    __shared__ __align__(16) __half As[2][128 * ASTH];
    __shared__ __align__(16) __half Bs[2][128 * ASTH];

    const int tid  = threadIdx.x;
    const int warp = tid >> 5;
    const int lane = tid & 31;
    const int g    = lane >> 2;
    const int tg   = lane & 3;
    const int wm   = warp >> 2;      // 0..1
    const int wn   = warp & 3;       // 0..3
    const int wmB  = wm * 64;
    const int wnB  = wn * 32;

    const int bm = blockIdx.y * 128;
    const int bn = blockIdx.x * 128;

    float acc[4][4][4];
#pragma unroll
    for (int mf = 0; mf < 4; mf++)
#pragma unroll
        for (int nf = 0; nf < 4; nf++)
#pragma unroll
            for (int i = 0; i < 4; i++) acc[mf][nf][i] = 0.f;

    // writer indexing: row = tid>>1 (0..127), 32B-half selector = tid&1
    const int wrow = tid >> 1;
    const int hsel = (tid & 1) * 16;         // halves offset within 32-half chunk

    // LDSM lane addressing
    const int rA  = lane & 15;
    const int cAb = (lane >> 4) * 16;        // bytes

    const uint32_t asb0 = (uint32_t)__cvta_generic_to_shared(&As[0][0]);
    const uint32_t asb1 = (uint32_t)__cvta_generic_to_shared(&As[1][0]);

    uint4 pa0, pa1, pb0, pb1;

    // prologue: chunk 0 -> stage 0
    {
        const __half* ag = A  + (size_t)(bm + wrow) * K + hsel;
        const __half* bg = Bt + (size_t)(bn + wrow) * K + hsel;
        pa0 = *(const uint4*)ag;  pa1 = *(const uint4*)(ag + 8);
        pb0 = *(const uint4*)bg;  pb1 = *(const uint4*)(bg + 8);
        *(uint4*)&As[0][wrow * ASTH + hsel]     = pa0;
        *(uint4*)&As[0][wrow * ASTH + hsel + 8] = pa1;
        *(uint4*)&Bs[0][wrow * ASTH + hsel]     = pb0;
        *(uint4*)&Bs[0][wrow * ASTH + hsel + 8] = pb1;
    }
    __syncthreads();

    const int nchunk = K / BKH;              // 32
    for (int ch = 0; ch < nchunk; ch++) {
        const int cur = ch & 1;
        const int nxt = cur ^ 1;
        const bool have_next = (ch + 1 < nchunk);

        if (have_next) {
            const int k0 = (ch + 1) * BKH;
            const __half* ag = A  + (size_t)(bm + wrow) * K + k0 + hsel;
            const __half* bg = Bt + (size_t)(bn + wrow) * K + k0 + hsel;
            pa0 = *(const uint4*)ag;  pa1 = *(const uint4*)(ag + 8);
            pb0 = *(const uint4*)bg;  pb1 = *(const uint4*)(bg + 8);
        }

        const uint32_t asbase = cur ? asb1 : asb0;
        const __half*  BsC    = &Bs[cur][0];

        // 2 k-steps of 16
#pragma unroll
        for (int s = 0; s < 2; s++) {
            uint32_t afr[4][4], bfr[4][2];
#pragma unroll
            for (int mf = 0; mf < 4; mf++) {
                uint32_t addr = asbase
                    + (uint32_t)((wmB + mf * 16 + rA) * (ASTH * 2))
                    + cAb + s * 32;
                ldsm_x4(afr[mf], addr);
            }
#pragma unroll
            for (int nf = 0; nf < 4; nf++) {
                const __half* bp = BsC + (wnB + nf * 8 + g) * ASTH + s * 16 + 2 * tg;
                bfr[nf][0] = *(const uint32_t*)bp;
                bfr[nf][1] = *(const uint32_t*)(bp + 8);
            }
#pragma unroll
            for (int mf = 0; mf < 4; mf++)
#pragma unroll
                for (int nf = 0; nf < 4; nf++)
                    mma_f16(acc[mf][nf], afr[mf], bfr[nf]);
        }

        if (have_next) {
            *(uint4*)&As[nxt][wrow * ASTH + hsel]     = pa0;
            *(uint4*)&As[nxt][wrow * ASTH + hsel + 8] = pa1;
            *(uint4*)&Bs[nxt][wrow * ASTH + hsel]     = pb0;
            *(uint4*)&Bs[nxt][wrow * ASTH + hsel + 8] = pb1;
            __syncthreads();
        }
    }

    // ---------------- epilogue ----------------
    if (MODE == 1) {
#pragma unroll
        for (int mf = 0; mf < 4; mf++) {
#pragma unroll
            for (int half = 0; half < 2; half++) {
                int gr = bm + wmB + mf * 16 + g + half * 8;
                if (gr >= M) continue;
#pragma unroll
                for (int nf = 0; nf < 4; nf++) {
                    int c = bn + wnB + nf * 8 + tg * 2;
                    *(float2*)&Cout[(size_t)gr * N + c] =
                        make_float2(acc[mf][nf][2 * half], acc[mf][nf][2 * half + 1]);
                }
            }
        }
    } else {
        int cwarp = bn + wnB;
        int which = cwarp >> 10;
        int h     = (cwarp & 1023) >> 6;
#pragma unroll
        for (int mf = 0; mf < 4; mf++) {
#pragma unroll
            for (int half = 0; half < 2; half++) {
                int gr = bm + wmB + mf * 16 + g + half * 8;
                if (gr >= M) continue;
                int b = gr / T_;
                int t = gr - b * T_;
                size_t rowbase = ((size_t)(b * H_ + h) * T_ + t) * D_;
#pragma unroll
                for (int nf = 0; nf < 4; nf++) {
                    int dbase = (wnB + nf * 8 + tg * 2) & 63;
                    float x0 = acc[mf][nf][2 * half];
                    float x1 = acc[mf][nf][2 * half + 1];
                    if (which == 2) {
                        *(float2*)&g_v[rowbase + dbase] = make_float2(x0, x1);
                    } else {
                        int pi = dbase >> 1;
                        float ct = g_cos[t * 32 + pi];
                        float st = g_sin[t * 32 + pi];
                        float* dst = (which == 0 ? g_q : g_k) + rowbase + dbase;
                        *(float2*)dst = make_float2(x0 * ct - x1 * st,
                                                    x1 * ct + x0 * st);
                    }
                }
            }
        }
    }
}

// ---------------------------------------------------------------------------
// Tensor-core flash attention (tf32 mma.sync) — unchanged except it writes
// fp16 into g_ya (feeds the fp16 proj GEMM).
// ---------------------------------------------------------------------------
#define AP 68   // smem row pad (words)

__global__ void __launch_bounds__(128) attn_tc_kernel() {
    const int qt = (int)gridDim.x - 1 - (int)blockIdx.x;  // heavy tiles first
    const int h  = blockIdx.y;
    const int b  = blockIdx.z;

    __shared__ uint32_t SmA[64 * AP];   // K tile, then P tile (and Q staging)
    __shared__ uint32_t SmV[64 * AP];   // V tile

    const int tid  = threadIdx.x;
    const int warp = tid >> 5;
    const int lane = tid & 31;
    const int g    = lane >> 2;
    const int tg   = lane & 3;
    const int qw   = warp * 16;

    const size_t base = (size_t)(b * H_ + h) * T_ * D_;

    float* Qs = (float*)SmA;
#pragma unroll
    for (int u = 0; u < 8; u++) {
        int i  = u * 128 + tid;
        int q  = i >> 4;
        int d4 = (i & 15) * 4;
        int row = min(qt * 64 + q, T_ - 1);
        *(float4*)&Qs[q * AP + d4] = *(const float4*)&g_q[base + (size_t)row * D_ + d4];
    }
    __syncthreads();

    uint32_t qb[8][2][2];
#pragma unroll
    for (int s = 0; s < 8; s++)
#pragma unroll
        for (int nf = 0; nf < 2; nf++) {
            int col = qw + nf * 8 + g;
            qb[s][nf][0] = f2tf32(Qs[col * AP + 8 * s + tg] * 0.125f);
            qb[s][nf][1] = f2tf32(Qs[col * AP + 8 * s + tg + 4] * 0.125f);
        }
    __syncthreads();

    float Ofr[8][4];
#pragma unroll
    for (int nf = 0; nf < 8; nf++)
#pragma unroll
        for (int i = 0; i < 4; i++) Ofr[nf][i] = 0.f;
    float mrun[4] = {-1e30f, -1e30f, -1e30f, -1e30f};
    float lrun[4] = {0.f, 0.f, 0.f, 0.f};

    const int srcl = (g >> 1) & 3;

    for (int kt = 0; kt <= qt; kt++) {
        const int kb = kt * 64;

#pragma unroll
        for (int u = 0; u < 8; u++) {
            int i  = u * 128 + tid;
            int kv = i >> 4;
            int d4 = (i & 15) * 4;
            int row = min(kb + kv, T_ - 1);
            float4 kk = *(const float4*)&g_k[base + (size_t)row * D_ + d4];
            float4 vv = *(const float4*)&g_v[base + (size_t)row * D_ + d4];
            *(uint4*)&SmA[kv * AP + d4] =
                make_uint4(f2tf32(kk.x), f2tf32(kk.y), f2tf32(kk.z), f2tf32(kk.w));
            *(uint4*)&SmV[kv * AP + d4] =
                make_uint4(f2tf32(vv.x), f2tf32(vv.y), f2tf32(vv.z), f2tf32(vv.w));
        }
        __syncthreads();

        float cS[4][2][4];
#pragma unroll
        for (int mf = 0; mf < 4; mf++)
#pragma unroll
            for (int nf = 0; nf < 2; nf++)
#pragma unroll
                for (int i = 0; i < 4; i++) cS[mf][nf][i] = 0.f;

#pragma unroll
        for (int s = 0; s < 8; s++) {
#pragma unroll
            for (int mf = 0; mf < 4; mf++) {
                uint32_t a[4];
                a[0] = SmA[(mf * 16 + g)     * AP + 8 * s + tg];
                a[1] = SmA[(mf * 16 + g + 8) * AP + 8 * s + tg];
                a[2] = SmA[(mf * 16 + g)     * AP + 8 * s + tg + 4];
                a[3] = SmA[(mf * 16 + g + 8) * AP + 8 * s + tg + 4];
                mma_tf32(cS[mf][0], a, qb[s][0]);
                mma_tf32(cS[mf][1], a, qb[s][1]);
            }
        }

        if (kt == qt) {
#pragma unroll
            for (int mf = 0; mf < 4; mf++)
#pragma unroll
                for (int nf = 0; nf < 2; nf++)
#pragma unroll
                    for (int i = 0; i < 4; i++) {
                        int kvg = kb + mf * 16 + g + (i >> 1) * 8;
                        int qg  = qt * 64 + qw + nf * 8 + 2 * tg + (i & 1);
                        if (kvg > qg) cS[mf][nf][i] = -1e30f;
                    }
        }

        float tmax[4];
#pragma unroll
        for (int nf = 0; nf < 2; nf++)
#pragma unroll
            for (int e = 0; e < 2; e++) {
                float v = -1e30f;
#pragma unroll
                for (int mf = 0; mf < 4; mf++)
                    v = fmaxf(v, fmaxf(cS[mf][nf][e], cS[mf][nf][2 + e]));
                tmax[nf * 2 + e] = v;
            }
#pragma unroll
        for (int st = 0; st < 4; st++) {
            tmax[st] = fmaxf(tmax[st], __shfl_xor_sync(0xffffffffu, tmax[st], 4));
            tmax[st] = fmaxf(tmax[st], __shfl_xor_sync(0xffffffffu, tmax[st], 8));
            tmax[st] = fmaxf(tmax[st], __shfl_xor_sync(0xffffffffu, tmax[st], 16));
        }
        float fst[4];
#pragma unroll
        for (int st = 0; st < 4; st++) {
            float mnew = fmaxf(mrun[st], tmax[st]);
            fst[st] = __expf(mrun[st] - mnew);
            mrun[st] = mnew;
            lrun[st] *= fst[st];
        }

#pragma unroll
        for (int mf = 0; mf < 4; mf++)
#pragma unroll
            for (int nf = 0; nf < 2; nf++)
#pragma unroll
                for (int i = 0; i < 4; i++) {
                    float p = __expf(cS[mf][nf][i] - mrun[nf * 2 + (i & 1)]);
                    cS[mf][nf][i] = p;
                    lrun[nf * 2 + (i & 1)] += p;
                }

        __syncthreads();

        uint32_t* Ps = SmA;
#pragma unroll
        for (int mf = 0; mf < 4; mf++)
#pragma unroll
            for (int nf = 0; nf < 2; nf++)
#pragma unroll
                for (int i = 0; i < 4; i++) {
                    int qloc = qw + nf * 8 + 2 * tg + (i & 1);
                    int kv   = mf * 16 + g + (i >> 1) * 8;
                    Ps[qloc * AP + kv] = f2tf32(cS[mf][nf][i]);
                }
        __syncwarp();

        {
            float f0 = __shfl_sync(0xffffffffu, fst[0], srcl);
            float f1 = __shfl_sync(0xffffffffu, fst[1], srcl);
            float f2 = __shfl_sync(0xffffffffu, fst[2], srcl);
            float f3 = __shfl_sync(0xffffffffu, fst[3], srcl);
            float fr0 = (g & 1) ? f1 : f0;
            float fr1 = (g & 1) ? f3 : f2;
#pragma unroll
            for (int nf = 0; nf < 8; nf++) {
                Ofr[nf][0] *= fr0;
                Ofr[nf][1] *= fr0;
                Ofr[nf][2] *= fr1;
                Ofr[nf][3] *= fr1;
            }
        }

#pragma unroll
        for (int s = 0; s < 8; s++) {
            uint32_t a[4];
            a[0] = Ps[(qw + g)     * AP + 8 * s + tg];
            a[1] = Ps[(qw + g + 8) * AP + 8 * s + tg];
            a[2] = Ps[(qw + g)     * AP + 8 * s + tg + 4];
            a[3] = Ps[(qw + g + 8) * AP + 8 * s + tg + 4];
#pragma unroll
            for (int nf = 0; nf < 8; nf++) {
                uint32_t bb[2];
                bb[0] = SmV[(8 * s + tg)     * AP + nf * 8 + g];
                bb[1] = SmV[(8 * s + tg + 4) * AP + nf * 8 + g];
                mma_tf32(Ofr[nf], a, bb);
            }
        }
        __syncthreads();
    }

#pragma unroll
    for (int st = 0; st < 4; st++) {
        lrun[st] += __shfl_xor_sync(0xffffffffu, lrun[st], 4);
        lrun[st] += __shfl_xor_sync(0xffffffffu, lrun[st], 8);
        lrun[st] += __shfl_xor_sync(0xffffffffu, lrun[st], 16);
    }

    float l0 = __shfl_sync(0xffffffffu, lrun[0], srcl);
    float l1 = __shfl_sync(0xffffffffu, lrun[1], srcl);
    float l2 = __shfl_sync(0xffffffffu, lrun[2], srcl);
    float l3 = __shfl_sync(0xffffffffu, lrun[3], srcl);
    float lr0 = (g & 1) ? l1 : l0;
    float lr1 = (g & 1) ? l3 : l2;
    float inv0 = 1.f / lr0;
    float inv1 = 1.f / lr1;

    int qg0 = qt * 64 + qw + g;
    int qg1 = qg0 + 8;
    if (qg0 < T_) {
        __half* yp = &g_ya[((size_t)(b * T_) + qg0) * C_ + h * D_];
#pragma unroll
        for (int nf = 0; nf < 8; nf++) {
            __half2 hv = __floats2half2_rn(Ofr[nf][0] * inv0, Ofr[nf][1] * inv0);
            *(__half2*)&yp[nf * 8 + 2 * tg] = hv;
        }
    }
    if (qg1 < T_) {
        __half* yp = &g_ya[((size_t)(b * T_) + qg1) * C_ + h * D_];
#pragma unroll
        for (int nf = 0; nf < 8; nf++) {
            __half2 hv = __floats2half2_rn(Ofr[nf][2] * inv1, Ofr[nf][3] * inv1);
            *(__half2*)&yp[nf * 8 + 2 * tg] = hv;
        }
    }
}

// ---------------------------------------------------------------------------
extern "C" void kernel_launch(void* const* d_in, const int* in_sizes, int n_in,
                              void* d_out, int out_size)
{
    const float* x      = (const float*)d_in[0];
    const float* W_attn = (const float*)d_in[2];
    const float* W_proj = (const float*)d_in[3];
    float* out = (float*)d_out;

    __half* xa;  cudaGetSymbolAddress((void**)&xa,  g_xa);
    __half* wat; cudaGetSymbolAddress((void**)&wat, g_wat);
    __half* wpt; cudaGetSymbolAddress((void**)&wpt, g_wpt);
    __half* ya;  cudaGetSymbolAddress((void**)&ya,  g_ya);

    rope_table_kernel<<<T_, 32>>>();

    cvt_h_kernel<<<(M_TOK*C_/4 + 255)/256, 256>>>((const float4*)x, (uint2*)xa, M_TOK*C_/4);
    transpose_h_kernel<<<dim3(3*C_/32, C_/32), dim3(32, 8)>>>(W_attn, wat, C_, 3*C_);
    transpose_h_kernel<<<dim3(C_/32,   C_/32), dim3(32, 8)>>>(W_proj, wpt, C_, C_);

    dim3 g_qkv(3072 / 128, MPAD / 128);            // 24 x 32
    gemm_f16<0><<<g_qkv, 256>>>(xa, wat, nullptr, M_TOK, 3072, 1024);

    dim3 g_attn((T_ + 63) / 64, H_, B_);           // 16 x 16 x 4
    attn_tc_kernel<<<g_attn, 128>>>();

    dim3 g_proj(1024 / 128, MPAD / 128);           // 8 x 32
    gemm_f16<1><<<g_proj, 256>>>(ya, wpt, out, M_TOK, 1024, 1024);
}

// round 14
// speedup vs baseline: 1.6983x; 1.2122x over previous
#include <cuda_runtime.h>
#include <cuda_fp16.h>
#include <math.h>
#include <stdint.h>

#define B_    4
#define T_    1000
#define C_    1024
#define H_    16
#define D_    64
#define M_TOK (B_*T_)   // 4000
#define MPAD  4096

// Scratch (allocation-free device globals; zero-init -> pad rows are 0)
__device__ __half g_q[B_*H_*T_*D_];
__device__ __half g_k[B_*H_*T_*D_];
__device__ __half g_v[B_*H_*T_*D_];
__device__ __half g_xa[MPAD*C_];     // x, fp16
__device__ __half g_ya[MPAD*C_];     // attention out, fp16
__device__ __half g_wat[3*C_*C_];    // W_attn^T [3072][1024] fp16
__device__ __half g_wpt[C_*C_];      // W_proj^T [1024][1024] fp16
__device__ float  g_cos[T_*(D_/2)];
__device__ float  g_sin[T_*(D_/2)];

// ---------------------------------------------------------------------------
__device__ __forceinline__ void mma_f16(float c[4],
                                        const uint32_t a[4],
                                        const uint32_t b[2]) {
    asm volatile(
        "mma.sync.aligned.m16n8k16.row.col.f32.f16.f16.f32 "
        "{%0,%1,%2,%3}, {%4,%5,%6,%7}, {%8,%9}, {%0,%1,%2,%3};"
        : "+f"(c[0]), "+f"(c[1]), "+f"(c[2]), "+f"(c[3])
        : "r"(a[0]), "r"(a[1]), "r"(a[2]), "r"(a[3]),
          "r"(b[0]), "r"(b[1]));
}

__device__ __forceinline__ void ldsm_x4(uint32_t r[4], uint32_t smaddr) {
    asm volatile(
        "ldmatrix.sync.aligned.m8n8.x4.shared.b16 {%0,%1,%2,%3}, [%4];"
        : "=r"(r[0]), "=r"(r[1]), "=r"(r[2]), "=r"(r[3])
        : "r"(smaddr));
}

__device__ __forceinline__ void ldsm_x4_t(uint32_t r[4], uint32_t smaddr) {
    asm volatile(
        "ldmatrix.sync.aligned.m8n8.x4.trans.shared.b16 {%0,%1,%2,%3}, [%4];"
        : "=r"(r[0]), "=r"(r[1]), "=r"(r[2]), "=r"(r[3])
        : "r"(smaddr));
}

// ---------------------------------------------------------------------------
__global__ void rope_table_kernel() {
    int t = blockIdx.x;
    int i = threadIdx.x;
    float theta = (float)pow(10000.0, -(double)(2 * i) / 64.0);
    float ang = (float)t * theta;
    g_cos[t * 32 + i] = cosf(ang);
    g_sin[t * 32 + i] = sinf(ang);
}

__global__ void cvt_h_kernel(const float4* __restrict__ src,
                             uint2* __restrict__ dst, int n4) {
    int i = blockIdx.x * blockDim.x + threadIdx.x;
    if (i < n4) {
        float4 v = src[i];
        __half2 h0 = __floats2half2_rn(v.x, v.y);
        __half2 h1 = __floats2half2_rn(v.z, v.w);
        uint2 o;
        o.x = *(uint32_t*)&h0;
        o.y = *(uint32_t*)&h1;
        dst[i] = o;
    }
}

__global__ void transpose_h_kernel(const float* __restrict__ src,
                                   __half* __restrict__ dst,
                                   int K, int N) {
    __shared__ float tile[32][33];
    int n0 = blockIdx.x * 32, k0 = blockIdx.y * 32;
    int tx = threadIdx.x, ty = threadIdx.y;
#pragma unroll
    for (int j = 0; j < 32; j += 8)
        tile[ty + j][tx] = src[(size_t)(k0 + ty + j) * N + n0 + tx];
    __syncthreads();
#pragma unroll
    for (int j = 0; j < 32; j += 8)
        dst[(size_t)(n0 + ty + j) * K + k0 + tx] = __float2half(tile[tx][ty + j]);
}

// ---------------------------------------------------------------------------
// 128x128 fp16 GEMM (R13, proven): 256 thr, warp 64x32, m16n8k16, BK=32.
// MODE 0: C = x @ W_attn, RoPE epilogue -> fp16 g_q/g_k/g_v.  MODE 1: -> f32 Cout.
// ---------------------------------------------------------------------------
#define BKH  32
#define ASTH 40

template<int MODE>
__global__ void __launch_bounds__(256, 2)
gemm_f16(const __half* __restrict__ A, const __half* __restrict__ Bt,
         float* __restrict__ Cout, int M, int N, int K)
{
    __shared__ __align__(16) __half As[2][128 * ASTH];
    __shared__ __align__(16) __half Bs[2][128 * ASTH];

    const int tid  = threadIdx.x;
    const int warp = tid >> 5;
    const int lane = tid & 31;
    const int g    = lane >> 2;
    const int tg   = lane & 3;
    const int wm   = warp >> 2;
    const int wn   = warp & 3;
    const int wmB  = wm * 64;
    const int wnB  = wn * 32;

    const int bm = blockIdx.y * 128;
    const int bn = blockIdx.x * 128;

    float acc[4][4][4];
#pragma unroll
    for (int mf = 0; mf < 4; mf++)
#pragma unroll
        for (int nf = 0; nf < 4; nf++)
#pragma unroll
            for (int i = 0; i < 4; i++) acc[mf][nf][i] = 0.f;

    const int wrow = tid >> 1;
    const int hsel = (tid & 1) * 16;

    const int rA  = lane & 15;
    const int cAb = (lane >> 4) * 16;

    const uint32_t asb0 = (uint32_t)__cvta_generic_to_shared(&As[0][0]);
    const uint32_t asb1 = (uint32_t)__cvta_generic_to_shared(&As[1][0]);

    uint4 pa0, pa1, pb0, pb1;
    {
        const __half* ag = A  + (size_t)(bm + wrow) * K + hsel;
        const __half* bg = Bt + (size_t)(bn + wrow) * K + hsel;
        pa0 = *(const uint4*)ag;  pa1 = *(const uint4*)(ag + 8);
        pb0 = *(const uint4*)bg;  pb1 = *(const uint4*)(bg + 8);
        *(uint4*)&As[0][wrow * ASTH + hsel]     = pa0;
        *(uint4*)&As[0][wrow * ASTH + hsel + 8] = pa1;
        *(uint4*)&Bs[0][wrow * ASTH + hsel]     = pb0;
        *(uint4*)&Bs[0][wrow * ASTH + hsel + 8] = pb1;
    }
    __syncthreads();

    const int nchunk = K / BKH;
    for (int ch = 0; ch < nchunk; ch++) {
        const int cur = ch & 1;
        const int nxt = cur ^ 1;
        const bool have_next = (ch + 1 < nchunk);

        if (have_next) {
            const int k0 = (ch + 1) * BKH;
            const __half* ag = A  + (size_t)(bm + wrow) * K + k0 + hsel;
            const __half* bg = Bt + (size_t)(bn + wrow) * K + k0 + hsel;
            pa0 = *(const uint4*)ag;  pa1 = *(const uint4*)(ag + 8);
            pb0 = *(const uint4*)bg;  pb1 = *(const uint4*)(bg + 8);
        }

        const uint32_t asbase = cur ? asb1 : asb0;
        const __half*  BsC    = &Bs[cur][0];

#pragma unroll
        for (int s = 0; s < 2; s++) {
            uint32_t afr[4][4], bfr[4][2];
#pragma unroll
            for (int mf = 0; mf < 4; mf++) {
                uint32_t addr = asbase
                    + (uint32_t)((wmB + mf * 16 + rA) * (ASTH * 2))
                    + cAb + s * 32;
                ldsm_x4(afr[mf], addr);
            }
#pragma unroll
            for (int nf = 0; nf < 4; nf++) {
                const __half* bp = BsC + (wnB + nf * 8 + g) * ASTH + s * 16 + 2 * tg;
                bfr[nf][0] = *(const uint32_t*)bp;
                bfr[nf][1] = *(const uint32_t*)(bp + 8);
            }
#pragma unroll
            for (int mf = 0; mf < 4; mf++)
#pragma unroll
                for (int nf = 0; nf < 4; nf++)
                    mma_f16(acc[mf][nf], afr[mf], bfr[nf]);
        }

        if (have_next) {
            *(uint4*)&As[nxt][wrow * ASTH + hsel]     = pa0;
            *(uint4*)&As[nxt][wrow * ASTH + hsel + 8] = pa1;
            *(uint4*)&Bs[nxt][wrow * ASTH + hsel]     = pb0;
            *(uint4*)&Bs[nxt][wrow * ASTH + hsel + 8] = pb1;
            __syncthreads();
        }
    }

    if (MODE == 1) {
#pragma unroll
        for (int mf = 0; mf < 4; mf++) {
#pragma unroll
            for (int half = 0; half < 2; half++) {
                int gr = bm + wmB + mf * 16 + g + half * 8;
                if (gr >= M) continue;
#pragma unroll
                for (int nf = 0; nf < 4; nf++) {
                    int c = bn + wnB + nf * 8 + tg * 2;
                    *(float2*)&Cout[(size_t)gr * N + c] =
                        make_float2(acc[mf][nf][2 * half], acc[mf][nf][2 * half + 1]);
                }
            }
        }
    } else {
        int cwarp = bn + wnB;
        int which = cwarp >> 10;
        int h     = (cwarp & 1023) >> 6;
#pragma unroll
        for (int mf = 0; mf < 4; mf++) {
#pragma unroll
            for (int half = 0; half < 2; half++) {
                int gr = bm + wmB + mf * 16 + g + half * 8;
                if (gr >= M) continue;
                int b = gr / T_;
                int t = gr - b * T_;
                size_t rowbase = ((size_t)(b * H_ + h) * T_ + t) * D_;
#pragma unroll
                for (int nf = 0; nf < 4; nf++) {
                    int dbase = (wnB + nf * 8 + tg * 2) & 63;
                    float x0 = acc[mf][nf][2 * half];
                    float x1 = acc[mf][nf][2 * half + 1];
                    if (which == 2) {
                        *(__half2*)&g_v[rowbase + dbase] = __floats2half2_rn(x0, x1);
                    } else {
                        int pi = dbase >> 1;
                        float ct = g_cos[t * 32 + pi];
                        float st = g_sin[t * 32 + pi];
                        __half* dst = (which == 0 ? g_q : g_k) + rowbase + dbase;
                        *(__half2*)dst = __floats2half2_rn(x0 * ct - x1 * st,
                                                           x1 * ct + x0 * st);
                    }
                }
            }
        }
    }
}

// ---------------------------------------------------------------------------
// fp16 tensor-core flash attention (m16n8k16).
// Block = 128 thr (4 warps), q-tile 64 (warp w: rows w*16..+15), kv-tile 64.
// Phase A: S^T = K·Q^T (K A-frags via LDSM, Q^T B-frags natural u32 loads).
// Phase B: O += P·V (P A-frags via LDSM, V B-frags via LDSM.trans).
// ---------------------------------------------------------------------------
#define KST 72    // halves per smem row (144B; 9*row mod 8 -> LDSM conflict-free)

__global__ void __launch_bounds__(128) attn_f16_kernel() {
    const int qt = (int)gridDim.x - 1 - (int)blockIdx.x;
    const int h  = blockIdx.y;
    const int b  = blockIdx.z;

    __shared__ __align__(16) __half SmK[64 * KST];  // Q staging, K tile, P tile
    __shared__ __align__(16) __half SmV[64 * KST];

    const int tid  = threadIdx.x;
    const int warp = tid >> 5;
    const int lane = tid & 31;
    const int g    = lane >> 2;
    const int tg   = lane & 3;
    const int qw   = warp * 16;

    const size_t base = (size_t)(b * H_ + h) * T_ * D_;

    const uint32_t kb_sm = (uint32_t)__cvta_generic_to_shared(SmK);
    const uint32_t vb_sm = (uint32_t)__cvta_generic_to_shared(SmV);

    // ---- stage Q tile (fp16), extract Q^T B-fragments ----
#pragma unroll
    for (int u = 0; u < 4; u++) {
        int i   = u * 128 + tid;
        int row = i >> 3;
        int c8  = (i & 7) * 8;
        int grow = min(qt * 64 + row, T_ - 1);
        *(uint4*)&SmK[row * KST + c8] = *(const uint4*)&g_q[base + (size_t)grow * D_ + c8];
    }
    __syncthreads();

    uint32_t qb[4][2][2];
#pragma unroll
    for (int s = 0; s < 4; s++)
#pragma unroll
        for (int nf = 0; nf < 2; nf++) {
            const __half* qp = &SmK[(qw + nf * 8 + g) * KST + s * 16 + 2 * tg];
            qb[s][nf][0] = *(const uint32_t*)qp;
            qb[s][nf][1] = *(const uint32_t*)(qp + 8);
        }
    __syncthreads();

    float Ofr[8][4];
#pragma unroll
    for (int nf = 0; nf < 8; nf++)
#pragma unroll
        for (int i = 0; i < 4; i++) Ofr[nf][i] = 0.f;
    float mrun[4] = {-1e30f, -1e30f, -1e30f, -1e30f};
    float lrun[4] = {0.f, 0.f, 0.f, 0.f};

    const int srcl = (g >> 1) & 3;

    for (int kt = 0; kt <= qt; kt++) {
        const int kb = kt * 64;

        // load K/V tiles (fp16, coalesced uint4)
#pragma unroll
        for (int u = 0; u < 4; u++) {
            int i   = u * 128 + tid;
            int row = i >> 3;
            int c8  = (i & 7) * 8;
            int grow = min(kb + row, T_ - 1);
            *(uint4*)&SmK[row * KST + c8] = *(const uint4*)&g_k[base + (size_t)grow * D_ + c8];
            *(uint4*)&SmV[row * KST + c8] = *(const uint4*)&g_v[base + (size_t)grow * D_ + c8];
        }
        __syncthreads();

        // ---- Phase A: S^T[kv][q] = K · Q^T ----
        float cS[4][2][4];
#pragma unroll
        for (int mf = 0; mf < 4; mf++)
#pragma unroll
            for (int nf = 0; nf < 2; nf++)
#pragma unroll
                for (int i = 0; i < 4; i++) cS[mf][nf][i] = 0.f;

#pragma unroll
        for (int s = 0; s < 4; s++) {
#pragma unroll
            for (int mf = 0; mf < 4; mf++) {
                uint32_t a[4];
                uint32_t addr = kb_sm + (uint32_t)(
                    ((mf * 16 + (lane & 15)) * KST + (lane >> 4) * 8 + s * 16) * 2);
                ldsm_x4(a, addr);
                mma_f16(cS[mf][0], a, qb[s][0]);
                mma_f16(cS[mf][1], a, qb[s][1]);
            }
        }

        // scale (f32), then causal mask on the diagonal tile
#pragma unroll
        for (int mf = 0; mf < 4; mf++)
#pragma unroll
            for (int nf = 0; nf < 2; nf++)
#pragma unroll
                for (int i = 0; i < 4; i++) cS[mf][nf][i] *= 0.125f;

        if (kt == qt) {
#pragma unroll
            for (int mf = 0; mf < 4; mf++)
#pragma unroll
                for (int nf = 0; nf < 2; nf++)
#pragma unroll
                    for (int i = 0; i < 4; i++) {
                        int kvg = kb + mf * 16 + g + (i >> 1) * 8;
                        int qg  = qt * 64 + qw + nf * 8 + 2 * tg + (i & 1);
                        if (kvg > qg) cS[mf][nf][i] = -1e30f;
                    }
        }

        // ---- online softmax over q-columns ----
        float tmax[4];
#pragma unroll
        for (int nf = 0; nf < 2; nf++)
#pragma unroll
            for (int e = 0; e < 2; e++) {
                float v = -1e30f;
#pragma unroll
                for (int mf = 0; mf < 4; mf++)
                    v = fmaxf(v, fmaxf(cS[mf][nf][e], cS[mf][nf][2 + e]));
                tmax[nf * 2 + e] = v;
            }
#pragma unroll
        for (int st = 0; st < 4; st++) {
            tmax[st] = fmaxf(tmax[st], __shfl_xor_sync(0xffffffffu, tmax[st], 4));
            tmax[st] = fmaxf(tmax[st], __shfl_xor_sync(0xffffffffu, tmax[st], 8));
            tmax[st] = fmaxf(tmax[st], __shfl_xor_sync(0xffffffffu, tmax[st], 16));
        }
        float fst[4];
#pragma unroll
        for (int st = 0; st < 4; st++) {
            float mnew = fmaxf(mrun[st], tmax[st]);
            fst[st] = __expf(mrun[st] - mnew);
            mrun[st] = mnew;
            lrun[st] *= fst[st];
        }

#pragma unroll
        for (int mf = 0; mf < 4; mf++)
#pragma unroll
            for (int nf = 0; nf < 2; nf++)
#pragma unroll
                for (int i = 0; i < 4; i++) {
                    float p = __expf(cS[mf][nf][i] - mrun[nf * 2 + (i & 1)]);
                    cS[mf][nf][i] = p;
                    lrun[nf * 2 + (i & 1)] += p;
                }

        __syncthreads();   // everyone done reading K (SmK) via LDSM

        // store P (fp16) -> Ps[q][kv]
        __half* Ps = SmK;
#pragma unroll
        for (int mf = 0; mf < 4; mf++)
#pragma unroll
            for (int nf = 0; nf < 2; nf++)
#pragma unroll
                for (int i = 0; i < 4; i++) {
                    int qloc = qw + nf * 8 + 2 * tg + (i & 1);
                    int kv   = mf * 16 + g + (i >> 1) * 8;
                    Ps[qloc * KST + kv] = __float2half(cS[mf][nf][i]);
                }
        __syncwarp();

        // rescale O
        {
            float f0 = __shfl_sync(0xffffffffu, fst[0], srcl);
            float f1 = __shfl_sync(0xffffffffu, fst[1], srcl);
            float f2 = __shfl_sync(0xffffffffu, fst[2], srcl);
            float f3 = __shfl_sync(0xffffffffu, fst[3], srcl);
            float fr0 = (g & 1) ? f1 : f0;
            float fr1 = (g & 1) ? f3 : f2;
#pragma unroll
            for (int nf = 0; nf < 8; nf++) {
                Ofr[nf][0] *= fr0;
                Ofr[nf][1] *= fr0;
                Ofr[nf][2] *= fr1;
                Ofr[nf][3] *= fr1;
            }
        }

        // ---- Phase B: O[q][d] += P · V ----
#pragma unroll
        for (int s = 0; s < 4; s++) {
            uint32_t aP[4];
            {
                uint32_t addr = kb_sm + (uint32_t)(
                    ((qw + (lane & 15)) * KST + (lane >> 4) * 8 + s * 16) * 2);
                ldsm_x4(aP, addr);
            }
#pragma unroll
            for (int np = 0; np < 4; np++) {
                uint32_t v4[4];
                uint32_t addr = vb_sm + (uint32_t)(
                    ((s * 16 + ((lane >> 3) & 1) * 8 + (lane & 7)) * KST
                     + np * 16 + (lane >> 4) * 8) * 2);
                ldsm_x4_t(v4, addr);
                uint32_t b0[2] = { v4[0], v4[1] };
                uint32_t b1[2] = { v4[2], v4[3] };
                mma_f16(Ofr[2 * np],     aP, b0);
                mma_f16(Ofr[2 * np + 1], aP, b1);
            }
        }
        __syncthreads();   // before next tile overwrites SmK/SmV
    }

    // reduce l across g-lanes
#pragma unroll
    for (int st = 0; st < 4; st++) {
        lrun[st] += __shfl_xor_sync(0xffffffffu, lrun[st], 4);
        lrun[st] += __shfl_xor_sync(0xffffffffu, lrun[st], 8);
        lrun[st] += __shfl_xor_sync(0xffffffffu, lrun[st], 16);
    }

    float l0 = __shfl_sync(0xffffffffu, lrun[0], srcl);
    float l1 = __shfl_sync(0xffffffffu, lrun[1], srcl);
    float l2 = __shfl_sync(0xffffffffu, lrun[2], srcl);
    float l3 = __shfl_sync(0xffffffffu, lrun[3], srcl);
    float lr0 = (g & 1) ? l1 : l0;
    float lr1 = (g & 1) ? l3 : l2;
    float inv0 = 1.f / lr0;
    float inv1 = 1.f / lr1;

    int qg0 = qt * 64 + qw + g;
    int qg1 = qg0 + 8;
    if (qg0 < T_) {
        __half* yp = &g_ya[((size_t)(b * T_) + qg0) * C_ + h * D_];
#pragma unroll
        for (int nf = 0; nf < 8; nf++)
            *(__half2*)&yp[nf * 8 + 2 * tg] =
                __floats2half2_rn(Ofr[nf][0] * inv0, Ofr[nf][1] * inv0);
    }
    if (qg1 < T_) {
        __half* yp = &g_ya[((size_t)(b * T_) + qg1) * C_ + h * D_];
#pragma unroll
        for (int nf = 0; nf < 8; nf++)
            *(__half2*)&yp[nf * 8 + 2 * tg] =
                __floats2half2_rn(Ofr[nf][2] * inv1, Ofr[nf][3] * inv1);
    }
}

// ---------------------------------------------------------------------------
extern "C" void kernel_launch(void* const* d_in, const int* in_sizes, int n_in,
                              void* d_out, int out_size)
{
    const float* x      = (const float*)d_in[0];
    const float* W_attn = (const float*)d_in[2];
    const float* W_proj = (const float*)d_in[3];
    float* out = (float*)d_out;

    __half* xa;  cudaGetSymbolAddress((void**)&xa,  g_xa);
    __half* wat; cudaGetSymbolAddress((void**)&wat, g_wat);
    __half* wpt; cudaGetSymbolAddress((void**)&wpt, g_wpt);
    __half* ya;  cudaGetSymbolAddress((void**)&ya,  g_ya);

    rope_table_kernel<<<T_, 32>>>();

    cvt_h_kernel<<<(M_TOK*C_/4 + 255)/256, 256>>>((const float4*)x, (uint2*)xa, M_TOK*C_/4);
    transpose_h_kernel<<<dim3(3*C_/32, C_/32), dim3(32, 8)>>>(W_attn, wat, C_, 3*C_);
    transpose_h_kernel<<<dim3(C_/32,   C_/32), dim3(32, 8)>>>(W_proj, wpt, C_, C_);

    dim3 g_qkv(3072 / 128, MPAD / 128);            // 24 x 32
    gemm_f16<0><<<g_qkv, 256>>>(xa, wat, nullptr, M_TOK, 3072, 1024);

    dim3 g_attn((T_ + 63) / 64, H_, B_);           // 16 x 16 x 4
    attn_f16_kernel<<<g_attn, 128>>>();

    dim3 g_proj(1024 / 128, MPAD / 128);           // 8 x 32
    gemm_f16<1><<<g_proj, 256>>>(ya, wpt, out, M_TOK, 1024, 1024);
}

// round 15
// speedup vs baseline: 2.2531x; 1.3267x over previous
#include <cuda_runtime.h>
#include <cuda_fp16.h>
#include <math.h>
#include <stdint.h>

#define B_    4
#define T_    1000
#define C_    1024
#define H_    16
#define D_    64
#define M_TOK (B_*T_)   // 4000
#define MPAD  4096

// Scratch (allocation-free device globals; zero-init -> pad rows are 0)
__device__ __half g_q[B_*H_*T_*D_];
__device__ __half g_k[B_*H_*T_*D_];
__device__ __half g_v[B_*H_*T_*D_];
__device__ __half g_xa[MPAD*C_];     // x, fp16
__device__ __half g_ya[MPAD*C_];     // attention out, fp16
__device__ __half g_wat[3*C_*C_];    // W_attn^T [3072][1024] fp16
__device__ __half g_wpt[C_*C_];      // W_proj^T [1024][1024] fp16
__device__ float  g_cos[T_*(D_/2)];
__device__ float  g_sin[T_*(D_/2)];

// ---------------------------------------------------------------------------
__device__ __forceinline__ void mma_f16(float c[4],
                                        const uint32_t a[4],
                                        const uint32_t b[2]) {
    asm volatile(
        "mma.sync.aligned.m16n8k16.row.col.f32.f16.f16.f32 "
        "{%0,%1,%2,%3}, {%4,%5,%6,%7}, {%8,%9}, {%0,%1,%2,%3};"
        : "+f"(c[0]), "+f"(c[1]), "+f"(c[2]), "+f"(c[3])
        : "r"(a[0]), "r"(a[1]), "r"(a[2]), "r"(a[3]),
          "r"(b[0]), "r"(b[1]));
}

__device__ __forceinline__ void ldsm_x4(uint32_t r[4], uint32_t smaddr) {
    asm volatile(
        "ldmatrix.sync.aligned.m8n8.x4.shared.b16 {%0,%1,%2,%3}, [%4];"
        : "=r"(r[0]), "=r"(r[1]), "=r"(r[2]), "=r"(r[3])
        : "r"(smaddr));
}

__device__ __forceinline__ void ldsm_x4_t(uint32_t r[4], uint32_t smaddr) {
    asm volatile(
        "ldmatrix.sync.aligned.m8n8.x4.trans.shared.b16 {%0,%1,%2,%3}, [%4];"
        : "=r"(r[0]), "=r"(r[1]), "=r"(r[2]), "=r"(r[3])
        : "r"(smaddr));
}

__device__ __forceinline__ void cp16(uint32_t smaddr, const void* gptr) {
    asm volatile("cp.async.cg.shared.global [%0], [%1], 16;"
                 :: "r"(smaddr), "l"(gptr));
}
__device__ __forceinline__ void cp_commit() {
    asm volatile("cp.async.commit_group;" ::: "memory");
}
__device__ __forceinline__ void cp_wait0() {
    asm volatile("cp.async.wait_group 0;" ::: "memory");
}

// ---------------------------------------------------------------------------
__global__ void rope_table_kernel() {
    int t = blockIdx.x;
    int i = threadIdx.x;
    float theta = (float)pow(10000.0, -(double)(2 * i) / 64.0);
    float ang = (float)t * theta;
    g_cos[t * 32 + i] = cosf(ang);
    g_sin[t * 32 + i] = sinf(ang);
}

__global__ void cvt_h_kernel(const float4* __restrict__ src,
                             uint2* __restrict__ dst, int n4) {
    int i = blockIdx.x * blockDim.x + threadIdx.x;
    if (i < n4) {
        float4 v = src[i];
        __half2 h0 = __floats2half2_rn(v.x, v.y);
        __half2 h1 = __floats2half2_rn(v.z, v.w);
        uint2 o;
        o.x = *(uint32_t*)&h0;
        o.y = *(uint32_t*)&h1;
        dst[i] = o;
    }
}

__global__ void transpose_h_kernel(const float* __restrict__ src,
                                   __half* __restrict__ dst,
                                   int K, int N) {
    __shared__ float tile[32][33];
    int n0 = blockIdx.x * 32, k0 = blockIdx.y * 32;
    int tx = threadIdx.x, ty = threadIdx.y;
#pragma unroll
    for (int j = 0; j < 32; j += 8)
        tile[ty + j][tx] = src[(size_t)(k0 + ty + j) * N + n0 + tx];
    __syncthreads();
#pragma unroll
    for (int j = 0; j < 32; j += 8)
        dst[(size_t)(n0 + ty + j) * K + k0 + tx] = __float2half(tile[tx][ty + j]);
}

// ---------------------------------------------------------------------------
// 128x128 fp16 GEMM v2: 256 thr / 8 warps (2m x 4n), warp 64x32, m16n8k16,
// BK=64 (4 k-steps of 16), cp.async double-buffered, LDSM for A AND B frags.
//  A smem: [m=128][k=64 halves], row stride 72 halves (144B, conflict-free).
//  B smem: [n=128][k=64 halves], row stride 72 halves.  B global: [N][K] fp16.
// MODE 0: C = x @ W_attn, RoPE epilogue -> fp16 g_q/g_k/g_v.  MODE 1: -> f32 Cout.
// ---------------------------------------------------------------------------
#define BKH   64
#define GST   72                                  // halves per smem row
#define A_SZ  (128 * GST * 2)                     // 18432 B per tile
#define STG   (2 * A_SZ)                          // A + B per stage
#define GEMM_SMEM (2 * STG)                       // 73728 B

template<int MODE>
__global__ void __launch_bounds__(256, 2)
gemm_f16(const __half* __restrict__ A, const __half* __restrict__ Bt,
         float* __restrict__ Cout, int M, int N, int K)
{
    extern __shared__ __align__(16) uint8_t dsm[];
    const uint32_t smb = (uint32_t)__cvta_generic_to_shared(dsm);

    const int tid  = threadIdx.x;
    const int warp = tid >> 5;
    const int lane = tid & 31;
    const int g    = lane >> 2;
    const int tg   = lane & 3;
    const int wm   = warp >> 2;
    const int wn   = warp & 3;
    const int wmB  = wm * 64;
    const int wnB  = wn * 32;

    const int bm = blockIdx.y * 128;
    const int bn = blockIdx.x * 128;

    float acc[4][4][4];
#pragma unroll
    for (int mf = 0; mf < 4; mf++)
#pragma unroll
        for (int nf = 0; nf < 4; nf++)
#pragma unroll
            for (int i = 0; i < 4; i++) acc[mf][nf][i] = 0.f;

    // LDSM lane addressing (A): row = tile_m + (lane&15), k-off = (lane>>4)*8
    const int rA  = lane & 15;
    const int cA  = (lane >> 4) * 8;               // halves
    // LDSM lane addressing (B, nf-pair): n = nfb*8 + (lane>>4)*8 + (lane&7),
    //                                    k-off = ((lane>>3)&1)*8
    const int rB  = (lane >> 4) * 8 + (lane & 7);
    const int cB  = ((lane >> 3) & 1) * 8;

    // writer: i = u*256+tid indexes uint4 (8 halves); row = i>>3, q = i&7
    const int nchunk = K / BKH;

    auto issue = [&](int ch, int s) {
        const int k0 = ch * BKH;
        const uint32_t ab = smb + (uint32_t)(s * STG);
        const uint32_t bb = ab + A_SZ;
#pragma unroll
        for (int u = 0; u < 4; u++) {
            int i   = u * 256 + tid;
            int row = i >> 3;
            int q8  = (i & 7) * 8;
            cp16(ab + (uint32_t)((row * GST + q8) * 2),
                 A + (size_t)(bm + row) * K + k0 + q8);
            cp16(bb + (uint32_t)((row * GST + q8) * 2),
                 Bt + (size_t)(bn + row) * K + k0 + q8);
        }
        cp_commit();
    };

    // prologue
    issue(0, 0);
    cp_wait0();
    __syncthreads();

    for (int ch = 0; ch < nchunk; ch++) {
        const int cur = ch & 1;
        const bool have_next = (ch + 1 < nchunk);

        if (have_next) issue(ch + 1, cur ^ 1);

        const uint32_t ab = smb + (uint32_t)(cur * STG);
        const uint32_t bb = ab + A_SZ;

#pragma unroll
        for (int s = 0; s < 4; s++) {
            uint32_t afr[4][4];
#pragma unroll
            for (int mf = 0; mf < 4; mf++) {
                uint32_t addr = ab + (uint32_t)(
                    ((wmB + mf * 16 + rA) * GST + s * 16 + cA) * 2);
                ldsm_x4(afr[mf], addr);
            }
            uint32_t bfr[4][2];
#pragma unroll
            for (int nfb = 0; nfb < 2; nfb++) {      // nf pairs {0,1},{2,3}
                uint32_t v4[4];
                uint32_t addr = bb + (uint32_t)(
                    ((wnB + nfb * 16 + rB) * GST + s * 16 + cB) * 2);
                ldsm_x4(v4, addr);
                bfr[2 * nfb][0]     = v4[0];
                bfr[2 * nfb][1]     = v4[1];
                bfr[2 * nfb + 1][0] = v4[2];
                bfr[2 * nfb + 1][1] = v4[3];
            }
#pragma unroll
            for (int mf = 0; mf < 4; mf++)
#pragma unroll
                for (int nf = 0; nf < 4; nf++)
                    mma_f16(acc[mf][nf], afr[mf], bfr[nf]);
        }

        if (have_next) {
            cp_wait0();
            __syncthreads();
        }
    }

    // ---------------- epilogue ----------------
    if (MODE == 1) {
#pragma unroll
        for (int mf = 0; mf < 4; mf++) {
#pragma unroll
            for (int half = 0; half < 2; half++) {
                int gr = bm + wmB + mf * 16 + g + half * 8;
                if (gr >= M) continue;
#pragma unroll
                for (int nf = 0; nf < 4; nf++) {
                    int c = bn + wnB + nf * 8 + tg * 2;
                    *(float2*)&Cout[(size_t)gr * N + c] =
                        make_float2(acc[mf][nf][2 * half], acc[mf][nf][2 * half + 1]);
                }
            }
        }
    } else {
        int cwarp = bn + wnB;
        int which = cwarp >> 10;
        int h     = (cwarp & 1023) >> 6;
#pragma unroll
        for (int mf = 0; mf < 4; mf++) {
#pragma unroll
            for (int half = 0; half < 2; half++) {
                int gr = bm + wmB + mf * 16 + g + half * 8;
                if (gr >= M) continue;
                int b = gr / T_;
                int t = gr - b * T_;
                size_t rowbase = ((size_t)(b * H_ + h) * T_ + t) * D_;
#pragma unroll
                for (int nf = 0; nf < 4; nf++) {
                    int dbase = (wnB + nf * 8 + tg * 2) & 63;
                    float x0 = acc[mf][nf][2 * half];
                    float x1 = acc[mf][nf][2 * half + 1];
                    if (which == 2) {
                        *(__half2*)&g_v[rowbase + dbase] = __floats2half2_rn(x0, x1);
                    } else {
                        int pi = dbase >> 1;
                        float ct = g_cos[t * 32 + pi];
                        float st = g_sin[t * 32 + pi];
                        __half* dst = (which == 0 ? g_q : g_k) + rowbase + dbase;
                        *(__half2*)dst = __floats2half2_rn(x0 * ct - x1 * st,
                                                           x1 * ct + x0 * st);
                    }
                }
            }
        }
    }
}

// ---------------------------------------------------------------------------
// fp16 tensor-core flash attention (m16n8k16) — unchanged from R14 (proven).
// ---------------------------------------------------------------------------
#define KST 72

__global__ void __launch_bounds__(128) attn_f16_kernel() {
    const int qt = (int)gridDim.x - 1 - (int)blockIdx.x;
    const int h  = blockIdx.y;
    const int b  = blockIdx.z;

    __shared__ __align__(16) __half SmK[64 * KST];
    __shared__ __align__(16) __half SmV[64 * KST];

    const int tid  = threadIdx.x;
    const int warp = tid >> 5;
    const int lane = tid & 31;
    const int g    = lane >> 2;
    const int tg   = lane & 3;
    const int qw   = warp * 16;

    const size_t base = (size_t)(b * H_ + h) * T_ * D_;

    const uint32_t kb_sm = (uint32_t)__cvta_generic_to_shared(SmK);
    const uint32_t vb_sm = (uint32_t)__cvta_generic_to_shared(SmV);

#pragma unroll
    for (int u = 0; u < 4; u++) {
        int i   = u * 128 + tid;
        int row = i >> 3;
        int c8  = (i & 7) * 8;
        int grow = min(qt * 64 + row, T_ - 1);
        *(uint4*)&SmK[row * KST + c8] = *(const uint4*)&g_q[base + (size_t)grow * D_ + c8];
    }
    __syncthreads();

    uint32_t qb[4][2][2];
#pragma unroll
    for (int s = 0; s < 4; s++)
#pragma unroll
        for (int nf = 0; nf < 2; nf++) {
            const __half* qp = &SmK[(qw + nf * 8 + g) * KST + s * 16 + 2 * tg];
            qb[s][nf][0] = *(const uint32_t*)qp;
            qb[s][nf][1] = *(const uint32_t*)(qp + 8);
        }
    __syncthreads();

    float Ofr[8][4];
#pragma unroll
    for (int nf = 0; nf < 8; nf++)
#pragma unroll
        for (int i = 0; i < 4; i++) Ofr[nf][i] = 0.f;
    float mrun[4] = {-1e30f, -1e30f, -1e30f, -1e30f};
    float lrun[4] = {0.f, 0.f, 0.f, 0.f};

    const int srcl = (g >> 1) & 3;

    for (int kt = 0; kt <= qt; kt++) {
        const int kb = kt * 64;

#pragma unroll
        for (int u = 0; u < 4; u++) {
            int i   = u * 128 + tid;
            int row = i >> 3;
            int c8  = (i & 7) * 8;
            int grow = min(kb + row, T_ - 1);
            *(uint4*)&SmK[row * KST + c8] = *(const uint4*)&g_k[base + (size_t)grow * D_ + c8];
            *(uint4*)&SmV[row * KST + c8] = *(const uint4*)&g_v[base + (size_t)grow * D_ + c8];
        }
        __syncthreads();

        float cS[4][2][4];
#pragma unroll
        for (int mf = 0; mf < 4; mf++)
#pragma unroll
            for (int nf = 0; nf < 2; nf++)
#pragma unroll
                for (int i = 0; i < 4; i++) cS[mf][nf][i] = 0.f;

#pragma unroll
        for (int s = 0; s < 4; s++) {
#pragma unroll
            for (int mf = 0; mf < 4; mf++) {
                uint32_t a[4];
                uint32_t addr = kb_sm + (uint32_t)(
                    ((mf * 16 + (lane & 15)) * KST + (lane >> 4) * 8 + s * 16) * 2);
                ldsm_x4(a, addr);
                mma_f16(cS[mf][0], a, qb[s][0]);
                mma_f16(cS[mf][1], a, qb[s][1]);
            }
        }

#pragma unroll
        for (int mf = 0; mf < 4; mf++)
#pragma unroll
            for (int nf = 0; nf < 2; nf++)
#pragma unroll
                for (int i = 0; i < 4; i++) cS[mf][nf][i] *= 0.125f;

        if (kt == qt) {
#pragma unroll
            for (int mf = 0; mf < 4; mf++)
#pragma unroll
                for (int nf = 0; nf < 2; nf++)
#pragma unroll
                    for (int i = 0; i < 4; i++) {
                        int kvg = kb + mf * 16 + g + (i >> 1) * 8;
                        int qg  = qt * 64 + qw + nf * 8 + 2 * tg + (i & 1);
                        if (kvg > qg) cS[mf][nf][i] = -1e30f;
                    }
        }

        float tmax[4];
#pragma unroll
        for (int nf = 0; nf < 2; nf++)
#pragma unroll
            for (int e = 0; e < 2; e++) {
                float v = -1e30f;
#pragma unroll
                for (int mf = 0; mf < 4; mf++)
                    v = fmaxf(v, fmaxf(cS[mf][nf][e], cS[mf][nf][2 + e]));
                tmax[nf * 2 + e] = v;
            }
#pragma unroll
        for (int st = 0; st < 4; st++) {
            tmax[st] = fmaxf(tmax[st], __shfl_xor_sync(0xffffffffu, tmax[st], 4));
            tmax[st] = fmaxf(tmax[st], __shfl_xor_sync(0xffffffffu, tmax[st], 8));
            tmax[st] = fmaxf(tmax[st], __shfl_xor_sync(0xffffffffu, tmax[st], 16));
        }
        float fst[4];
#pragma unroll
        for (int st = 0; st < 4; st++) {
            float mnew = fmaxf(mrun[st], tmax[st]);
            fst[st] = __expf(mrun[st] - mnew);
            mrun[st] = mnew;
            lrun[st] *= fst[st];
        }

#pragma unroll
        for (int mf = 0; mf < 4; mf++)
#pragma unroll
            for (int nf = 0; nf < 2; nf++)
#pragma unroll
                for (int i = 0; i < 4; i++) {
                    float p = __expf(cS[mf][nf][i] - mrun[nf * 2 + (i & 1)]);
                    cS[mf][nf][i] = p;
                    lrun[nf * 2 + (i & 1)] += p;
                }

        __syncthreads();

        __half* Ps = SmK;
#pragma unroll
        for (int mf = 0; mf < 4; mf++)
#pragma unroll
            for (int nf = 0; nf < 2; nf++)
#pragma unroll
                for (int i = 0; i < 4; i++) {
                    int qloc = qw + nf * 8 + 2 * tg + (i & 1);
                    int kv   = mf * 16 + g + (i >> 1) * 8;
                    Ps[qloc * KST + kv] = __float2half(cS[mf][nf][i]);
                }
        __syncwarp();

        {
            float f0 = __shfl_sync(0xffffffffu, fst[0], srcl);
            float f1 = __shfl_sync(0xffffffffu, fst[1], srcl);
            float f2 = __shfl_sync(0xffffffffu, fst[2], srcl);
            float f3 = __shfl_sync(0xffffffffu, fst[3], srcl);
            float fr0 = (g & 1) ? f1 : f0;
            float fr1 = (g & 1) ? f3 : f2;
#pragma unroll
            for (int nf = 0; nf < 8; nf++) {
                Ofr[nf][0] *= fr0;
                Ofr[nf][1] *= fr0;
                Ofr[nf][2] *= fr1;
                Ofr[nf][3] *= fr1;
            }
        }

#pragma unroll
        for (int s = 0; s < 4; s++) {
            uint32_t aP[4];
            {
                uint32_t addr = kb_sm + (uint32_t)(
                    ((qw + (lane & 15)) * KST + (lane >> 4) * 8 + s * 16) * 2);
                ldsm_x4(aP, addr);
            }
#pragma unroll
            for (int np = 0; np < 4; np++) {
                uint32_t v4[4];
                uint32_t addr = vb_sm + (uint32_t)(
                    ((s * 16 + ((lane >> 3) & 1) * 8 + (lane & 7)) * KST
                     + np * 16 + (lane >> 4) * 8) * 2);
                ldsm_x4_t(v4, addr);
                uint32_t b0[2] = { v4[0], v4[1] };
                uint32_t b1[2] = { v4[2], v4[3] };
                mma_f16(Ofr[2 * np],     aP, b0);
                mma_f16(Ofr[2 * np + 1], aP, b1);
            }
        }
        __syncthreads();
    }

#pragma unroll
    for (int st = 0; st < 4; st++) {
        lrun[st] += __shfl_xor_sync(0xffffffffu, lrun[st], 4);
        lrun[st] += __shfl_xor_sync(0xffffffffu, lrun[st], 8);
        lrun[st] += __shfl_xor_sync(0xffffffffu, lrun[st], 16);
    }

    float l0 = __shfl_sync(0xffffffffu, lrun[0], srcl);
    float l1 = __shfl_sync(0xffffffffu, lrun[1], srcl);
    float l2 = __shfl_sync(0xffffffffu, lrun[2], srcl);
    float l3 = __shfl_sync(0xffffffffu, lrun[3], srcl);
    float lr0 = (g & 1) ? l1 : l0;
    float lr1 = (g & 1) ? l3 : l2;
    float inv0 = 1.f / lr0;
    float inv1 = 1.f / lr1;

    int qg0 = qt * 64 + qw + g;
    int qg1 = qg0 + 8;
    if (qg0 < T_) {
        __half* yp = &g_ya[((size_t)(b * T_) + qg0) * C_ + h * D_];
#pragma unroll
        for (int nf = 0; nf < 8; nf++)
            *(__half2*)&yp[nf * 8 + 2 * tg] =
                __floats2half2_rn(Ofr[nf][0] * inv0, Ofr[nf][1] * inv0);
    }
    if (qg1 < T_) {
        __half* yp = &g_ya[((size_t)(b * T_) + qg1) * C_ + h * D_];
#pragma unroll
        for (int nf = 0; nf < 8; nf++)
            *(__half2*)&yp[nf * 8 + 2 * tg] =
                __floats2half2_rn(Ofr[nf][2] * inv1, Ofr[nf][3] * inv1);
    }
}

// ---------------------------------------------------------------------------
extern "C" void kernel_launch(void* const* d_in, const int* in_sizes, int n_in,
                              void* d_out, int out_size)
{
    const float* x      = (const float*)d_in[0];
    const float* W_attn = (const float*)d_in[2];
    const float* W_proj = (const float*)d_in[3];
    float* out = (float*)d_out;

    __half* xa;  cudaGetSymbolAddress((void**)&xa,  g_xa);
    __half* wat; cudaGetSymbolAddress((void**)&wat, g_wat);
    __half* wpt; cudaGetSymbolAddress((void**)&wpt, g_wpt);
    __half* ya;  cudaGetSymbolAddress((void**)&ya,  g_ya);

    cudaFuncSetAttribute(gemm_f16<0>, cudaFuncAttributeMaxDynamicSharedMemorySize, GEMM_SMEM);
    cudaFuncSetAttribute(gemm_f16<1>, cudaFuncAttributeMaxDynamicSharedMemorySize, GEMM_SMEM);

    rope_table_kernel<<<T_, 32>>>();

    cvt_h_kernel<<<(M_TOK*C_/4 + 255)/256, 256>>>((const float4*)x, (uint2*)xa, M_TOK*C_/4);
    transpose_h_kernel<<<dim3(3*C_/32, C_/32), dim3(32, 8)>>>(W_attn, wat, C_, 3*C_);
    transpose_h_kernel<<<dim3(C_/32,   C_/32), dim3(32, 8)>>>(W_proj, wpt, C_, C_);

    dim3 g_qkv(3072 / 128, MPAD / 128);            // 24 x 32
    gemm_f16<0><<<g_qkv, 256, GEMM_SMEM>>>(xa, wat, nullptr, M_TOK, 3072, 1024);

    dim3 g_attn((T_ + 63) / 64, H_, B_);           // 16 x 16 x 4
    attn_f16_kernel<<<g_attn, 128>>>();

    dim3 g_proj(1024 / 128, MPAD / 128);           // 8 x 32
    gemm_f16<1><<<g_proj, 256, GEMM_SMEM>>>(ya, wpt, out, M_TOK, 1024, 1024);
}